// round 1
// baseline (speedup 1.0000x reference)
#include <cuda_runtime.h>
#include <math.h>

#define BB   2048
#define TT   48
#define HH   512
#define EE   256
#define VV   128
#define ENCC 1024
#define H3   1536

// ---------------- scratch (device globals; no allocations allowed) ----------
__device__ float g_x1[(size_t)BB * TT * H3];     // [B,T,3H] precomputed emb@k1+b1[0]
__device__ float g_seq2[(size_t)BB * TT * HH];   // [B,T,H] layer-2 outputs
__device__ float g_h1[BB * HH];
__device__ float g_h2[BB * HH];
__device__ float g_inner1[BB * H3];
__device__ float g_xg2[BB * H3];
__device__ float g_inner2[BB * H3];

// ---------------- generic tiled SGEMM: C = op(A) @ B (+bias) ----------------
// A: [M,K] row-major (or gathered rows table[ids[m]]), B: [K,N] row-major.
// Up to 3 independent jobs selected by blockIdx.z (same M,N,K).
struct Job {
    const float* A;
    const float* Bm;
    const float* bias;   // nullable, length N
    float*       C;
    const int*   ids;    // nullable -> gather mode: row m of A = table[ids[m]]
    const float* table;
};

__global__ __launch_bounds__(256)
void sgemm_kernel(Job j0, Job j1, Job j2, int M, int N, int K) {
    Job jb = (blockIdx.z == 0) ? j0 : (blockIdx.z == 1) ? j1 : j2;

    __shared__ float As[8][128];
    __shared__ float Bs[8][128];
    __shared__ int   ids_s[128];

    const int tid = threadIdx.x;
    const int bm  = blockIdx.y * 128;
    const int bn  = blockIdx.x * 128;

    const int arow = tid >> 1;          // 0..127
    const int acol = (tid & 1) * 4;     // 0 or 4
    const int brow = tid >> 5;          // 0..7
    const int bcol = (tid & 31) * 4;    // 0..124

    const float* arow_ptr;
    if (jb.ids) {
        if (tid < 128) ids_s[tid] = jb.ids[bm + tid];
        __syncthreads();
        arow_ptr = jb.table + (size_t)ids_s[arow] * K;
    } else {
        arow_ptr = jb.A + (size_t)(bm + arow) * K;
    }
    const float* bptr = jb.Bm + (size_t)brow * N + bn + bcol;

    float acc[8][8];
#pragma unroll
    for (int i = 0; i < 8; i++)
#pragma unroll
        for (int j = 0; j < 8; j++) acc[i][j] = 0.f;

    const int ty = tid >> 4;   // 0..15
    const int tx = tid & 15;   // 0..15

    for (int k0 = 0; k0 < K; k0 += 8) {
        float4 av = *(const float4*)(arow_ptr + k0 + acol);
        float4 bv = *(const float4*)(bptr + (size_t)k0 * N);
        __syncthreads();
        As[acol + 0][arow] = av.x;
        As[acol + 1][arow] = av.y;
        As[acol + 2][arow] = av.z;
        As[acol + 3][arow] = av.w;
        *(float4*)&Bs[brow][bcol] = bv;
        __syncthreads();
#pragma unroll
        for (int kk = 0; kk < 8; kk++) {
            float4 a0 = *(const float4*)&As[kk][ty * 8];
            float4 a1 = *(const float4*)&As[kk][ty * 8 + 4];
            float4 b0 = *(const float4*)&Bs[kk][tx * 8];
            float4 b1 = *(const float4*)&Bs[kk][tx * 8 + 4];
            float a[8] = {a0.x, a0.y, a0.z, a0.w, a1.x, a1.y, a1.z, a1.w};
            float b[8] = {b0.x, b0.y, b0.z, b0.w, b1.x, b1.y, b1.z, b1.w};
#pragma unroll
            for (int i = 0; i < 8; i++)
#pragma unroll
                for (int j = 0; j < 8; j++)
                    acc[i][j] = fmaf(a[i], b[j], acc[i][j]);
        }
    }

    float bb[8];
#pragma unroll
    for (int j = 0; j < 8; j++)
        bb[j] = jb.bias ? jb.bias[bn + tx * 8 + j] : 0.f;

#pragma unroll
    for (int i = 0; i < 8; i++) {
        float* crow = jb.C + (size_t)(bm + ty * 8 + i) * N + bn + tx * 8;
        float4 c0 = {acc[i][0] + bb[0], acc[i][1] + bb[1], acc[i][2] + bb[2], acc[i][3] + bb[3]};
        float4 c1 = {acc[i][4] + bb[4], acc[i][5] + bb[5], acc[i][6] + bb[6], acc[i][7] + bb[7]};
        *(float4*)crow       = c0;
        *(float4*)(crow + 4) = c1;
    }
}

// ---------------- GRU elementwise gate update (Keras reset_after, z|r|h) -----
__device__ __forceinline__ float sigmoidf_(float x) { return 1.f / (1.f + expf(-x)); }

__global__ void gru_update_kernel(const float* __restrict__ xg_base, size_t xg_stride,
                                  const float* __restrict__ inner,
                                  float* __restrict__ h,
                                  const int* __restrict__ tgt, int t,
                                  float* __restrict__ seq_out, size_t seq_stride) {
    int idx = blockIdx.x * blockDim.x + threadIdx.x;   // < B*H
    int b = idx >> 9;            // H == 512
    int j = idx & (HH - 1);
    float hv = h[idx];
    if (tgt[b * TT + t] != 0) {  // mask_zero: only update on non-pad tokens
        const float* xg = xg_base + (size_t)b * xg_stride;
        const float* in = inner + (size_t)b * H3;
        float z  = sigmoidf_(xg[j]          + in[j]);
        float r  = sigmoidf_(xg[HH + j]     + in[HH + j]);
        float hh = tanhf    (xg[2 * HH + j] + r * in[2 * HH + j]);
        hv = z * hv + (1.f - z) * hh;
        h[idx] = hv;
    }
    if (seq_out) seq_out[(size_t)b * seq_stride + j] = hv;  // output==state (also on masked steps)
}

// ---------------- in-place softmax over V=128 (1 warp / row, 4 elems/lane) ---
__global__ void softmax_kernel(float* __restrict__ out) {
    int row  = blockIdx.x * 8 + (threadIdx.x >> 5);
    int lane = threadIdx.x & 31;
    float* p = out + (size_t)row * VV + lane * 4;
    float4 v = *(float4*)p;
    float m = fmaxf(fmaxf(v.x, v.y), fmaxf(v.z, v.w));
#pragma unroll
    for (int o = 16; o > 0; o >>= 1) m = fmaxf(m, __shfl_xor_sync(0xffffffffu, m, o));
    v.x = expf(v.x - m); v.y = expf(v.y - m); v.z = expf(v.z - m); v.w = expf(v.w - m);
    float s = v.x + v.y + v.z + v.w;
#pragma unroll
    for (int o = 16; o > 0; o >>= 1) s += __shfl_xor_sync(0xffffffffu, s, o);
    float inv = 1.f / s;
    v.x *= inv; v.y *= inv; v.z *= inv; v.w *= inv;
    *(float4*)p = v;
}

// ---------------- launch ----------------------------------------------------
extern "C" void kernel_launch(void* const* d_in, const int* in_sizes, int n_in,
                              void* d_out, int out_size) {
    const int*   tgt = (const int*)  d_in[0];
    const float* enc = (const float*)d_in[1];
    const float* Wi1 = (const float*)d_in[2];
    const float* Wi2 = (const float*)d_in[3];
    const float* emb = (const float*)d_in[4];
    const float* k1  = (const float*)d_in[5];
    const float* rk1 = (const float*)d_in[6];
    const float* b1  = (const float*)d_in[7];
    const float* k2  = (const float*)d_in[8];
    const float* rk2 = (const float*)d_in[9];
    const float* b2  = (const float*)d_in[10];
    const float* Wv  = (const float*)d_in[11];
    const float* bv  = (const float*)d_in[12];
    float* out = (float*)d_out;

    float *x1, *seq2, *h1, *h2, *in1, *xg2, *in2;
    cudaGetSymbolAddress((void**)&x1,   g_x1);
    cudaGetSymbolAddress((void**)&seq2, g_seq2);
    cudaGetSymbolAddress((void**)&h1,   g_h1);
    cudaGetSymbolAddress((void**)&h2,   g_h2);
    cudaGetSymbolAddress((void**)&in1,  g_inner1);
    cudaGetSymbolAddress((void**)&xg2,  g_xg2);
    cudaGetSymbolAddress((void**)&in2,  g_inner2);

    dim3 blk(256);

    // h01 = enc@Wi1 ; h02 = enc@Wi2   (two jobs via z)
    {
        Job a = {enc, Wi1, nullptr, h1, nullptr, nullptr};
        Job b = {enc, Wi2, nullptr, h2, nullptr, nullptr};
        sgemm_kernel<<<dim3(HH / 128, BB / 128, 2), blk>>>(a, b, a, BB, HH, ENCC);
    }
    // x1 = gather(embed, tgt) @ k1 + b1[0]   over all B*T rows
    {
        Job a = {nullptr, k1, b1, x1, tgt, emb};
        sgemm_kernel<<<dim3(H3 / 128, (BB * TT) / 128, 1), blk>>>(a, a, a, BB * TT, H3, EE);
    }
    // inner1(t=0) = h1 @ rk1 + b1[1]
    {
        Job a = {h1, rk1, b1 + H3, in1, nullptr, nullptr};
        sgemm_kernel<<<dim3(H3 / 128, BB / 128, 1), blk>>>(a, a, a, BB, H3, HH);
    }

    const int nthr = BB * HH;
    for (int t = 0; t < TT; t++) {
        // layer-1 gate update (reads x1[:,t], inner1 -> updates h1)
        gru_update_kernel<<<nthr / 256, blk>>>(x1 + (size_t)t * H3, (size_t)TT * H3,
                                               in1, h1, tgt, t, nullptr, 0);
        // fused 3-way GEMM: xg2 = h1@k2+b2[0]; inner2 = h2@rk2+b2[1]; inner1 = h1@rk1+b1[1] (for t+1)
        {
            Job a = {h1, k2,  b2,      xg2, nullptr, nullptr};
            Job b = {h2, rk2, b2 + H3, in2, nullptr, nullptr};
            Job c = {h1, rk1, b1 + H3, in1, nullptr, nullptr};
            sgemm_kernel<<<dim3(H3 / 128, BB / 128, 3), blk>>>(a, b, c, BB, H3, HH);
        }
        // layer-2 gate update; also emit seq2[:,t]
        gru_update_kernel<<<nthr / 256, blk>>>(xg2, H3, in2, h2, tgt, t,
                                               seq2 + (size_t)t * HH, (size_t)TT * HH);
    }

    // logits = seq2 @ Wv + bv  (written straight into d_out), then in-place softmax
    {
        Job a = {seq2, Wv, bv, out, nullptr, nullptr};
        sgemm_kernel<<<dim3(VV / 128, (BB * TT) / 128, 1), blk>>>(a, a, a, BB * TT, VV, HH);
    }
    softmax_kernel<<<(BB * TT) / 8, blk>>>(out);
}

// round 4
// speedup vs baseline: 1.9865x; 1.9865x over previous
#include <cuda_runtime.h>
#include <cuda_bf16.h>
#include <stdint.h>
#include <math.h>

#define BB   2048
#define TT   48
#define HH   512
#define EE   256
#define VV   128
#define ENCC 1024
#define H3   1536

// ===================== stable-ISA PTX helpers (sm_80+) ======================
__device__ __forceinline__ uint32_t smem_u32(const void* p) {
    uint32_t a;
    asm("{ .reg .u64 t; cvta.to.shared.u64 t, %1; cvt.u32.u64 %0, t; }" : "=r"(a) : "l"(p));
    return a;
}
__device__ __forceinline__ void cp_async16(uint32_t dst, const void* src) {
    asm volatile("cp.async.cg.shared.global [%0], [%1], 16;" :: "r"(dst), "l"(src));
}
#define CP_COMMIT() asm volatile("cp.async.commit_group;" ::: "memory")
#define CP_WAIT1()  asm volatile("cp.async.wait_group 1;" ::: "memory")

__device__ __forceinline__ void ldsm_x4(uint32_t* r, uint32_t addr) {
    asm volatile("ldmatrix.sync.aligned.m8n8.x4.shared.b16 {%0,%1,%2,%3}, [%4];"
                 : "=r"(r[0]), "=r"(r[1]), "=r"(r[2]), "=r"(r[3]) : "r"(addr));
}
__device__ __forceinline__ void ldsm_x2(uint32_t* r, uint32_t addr) {
    asm volatile("ldmatrix.sync.aligned.m8n8.x2.shared.b16 {%0,%1}, [%2];"
                 : "=r"(r[0]), "=r"(r[1]) : "r"(addr));
}
__device__ __forceinline__ void mma16816(float* d, const uint32_t* a, const uint32_t* b) {
    asm volatile("mma.sync.aligned.m16n8k16.row.col.f32.bf16.bf16.f32 "
                 "{%0,%1,%2,%3}, {%4,%5,%6,%7}, {%8,%9}, {%0,%1,%2,%3};"
                 : "+f"(d[0]), "+f"(d[1]), "+f"(d[2]), "+f"(d[3])
                 : "r"(a[0]), "r"(a[1]), "r"(a[2]), "r"(a[3]), "r"(b[0]), "r"(b[1]));
}

// ===================== device scratch (no allocations) ======================
__device__ __align__(16) float g_x1 [(size_t)BB * TT * H3];
__device__ __align__(16) float g_h1 [BB * HH];
__device__ __align__(16) float g_h2 [BB * HH];
__device__ __align__(16) float g_in1[BB * H3];
__device__ __align__(16) float g_xg2[BB * H3];
__device__ __align__(16) float g_in2[BB * H3];

__device__ __align__(16) __nv_bfloat16 g_h1h[BB * HH], g_h1l[BB * HH];
__device__ __align__(16) __nv_bfloat16 g_h2h[BB * HH], g_h2l[BB * HH];
__device__ __align__(16) __nv_bfloat16 g_seqh[(size_t)BB * TT * HH], g_seql[(size_t)BB * TT * HH];
__device__ __align__(16) __nv_bfloat16 g_ench[BB * ENCC], g_encl[BB * ENCC];

// transposed/split weights: [N,K] row-major, bf16 hi/lo
__device__ __align__(16) __nv_bfloat16 g_k1h [H3 * EE],   g_k1l [H3 * EE];
__device__ __align__(16) __nv_bfloat16 g_rk1h[H3 * HH],   g_rk1l[H3 * HH];
__device__ __align__(16) __nv_bfloat16 g_k2h [H3 * HH],   g_k2l [H3 * HH];
__device__ __align__(16) __nv_bfloat16 g_rk2h[H3 * HH],   g_rk2l[H3 * HH];
__device__ __align__(16) __nv_bfloat16 g_wi1h[HH * ENCC], g_wi1l[HH * ENCC];
__device__ __align__(16) __nv_bfloat16 g_wi2h[HH * ENCC], g_wi2l[HH * ENCC];
__device__ __align__(16) __nv_bfloat16 g_wvh [VV * HH],   g_wvl [VV * HH];
__device__ __align__(16) __nv_bfloat16 g_embh[VV * EE],   g_embl[VV * EE];

__device__ __forceinline__ void split2(float v, __nv_bfloat16& h, __nv_bfloat16& l) {
    h = __float2bfloat16(v);
    l = __float2bfloat16(v - __bfloat162float(h));
}

// ===================== prep: transpose + hi/lo split ========================
__global__ __launch_bounds__(256)
void tsplit_kernel(const float* __restrict__ W, __nv_bfloat16* __restrict__ Th,
                   __nv_bfloat16* __restrict__ Tl, int K, int N) {
    __shared__ float s[32][33];
    int n0 = blockIdx.x * 32, k0 = blockIdx.y * 32;
    int tx = threadIdx.x & 31, ty = threadIdx.x >> 5;
#pragma unroll
    for (int i = 0; i < 32; i += 8)
        s[ty + i][tx] = W[(size_t)(k0 + ty + i) * N + n0 + tx];
    __syncthreads();
#pragma unroll
    for (int i = 0; i < 32; i += 8) {
        float v = s[tx][ty + i];
        __nv_bfloat16 h, l; split2(v, h, l);
        size_t o = (size_t)(n0 + ty + i) * K + k0 + tx;
        Th[o] = h; Tl[o] = l;
    }
}

__global__ __launch_bounds__(256)
void split_kernel(const float* __restrict__ src, __nv_bfloat16* __restrict__ dh,
                  __nv_bfloat16* __restrict__ dl, int n4) {
    int i = blockIdx.x * 256 + threadIdx.x;
    if (i >= n4) return;
    float4 v = ((const float4*)src)[i];
    __nv_bfloat16 h0,l0,h1,l1,h2,l2,h3,l3;
    split2(v.x,h0,l0); split2(v.y,h1,l1); split2(v.z,h2,l2); split2(v.w,h3,l3);
    ((__nv_bfloat162*)dh)[2*i]   = __nv_bfloat162(h0,h1);
    ((__nv_bfloat162*)dh)[2*i+1] = __nv_bfloat162(h2,h3);
    ((__nv_bfloat162*)dl)[2*i]   = __nv_bfloat162(l0,l1);
    ((__nv_bfloat162*)dl)[2*i+1] = __nv_bfloat162(l2,l3);
}

// ===================== mma.sync split-bf16 GEMM =============================
// C[M,N] = A[M,K] @ W[K,N] computed as D[m,n] = sum_k As[m,k] * Bs[n,k]
// with Bs = W^T stored [N,K]. Split: C = Ah*Bh + Ah*Bl + Al*Bh (3 passes).
struct TJob {
    const __nv_bfloat16 *Ah, *Al;   // [M,K] (or gather tables [V,K])
    const __nv_bfloat16 *Bh, *Bl;   // [N,K]
    const float* bias;              // len N, nullable
    float* C;                       // [M,N]
    __nv_bfloat16 *Ch, *Cl;         // optional split copy of C
    const int* ids;                 // gather row ids (nullable)
};

// tile: BM=128, BN=128, Kc=32. 8 warps, each 64x32. padded rows of 40 bf16.
#define LDP 40
#define OFF_IDS 0
#define OFF_A0  1024
#define OFF_B0  (OFF_A0 + 128 * LDP * 2)
#define OFF_A1  (OFF_B0 + 128 * LDP * 2)
#define OFF_B1  (OFF_A1 + 128 * LDP * 2)
#define SMEM_SZ (OFF_B1 + 128 * LDP * 2)

__global__ __launch_bounds__(256, 2)
void tc_gemm(TJob j0, TJob j1, TJob j2, int K, int N) {
    __shared__ __align__(16) char smem[SMEM_SZ];
    const TJob& jb = (blockIdx.z == 0) ? j0 : (blockIdx.z == 1) ? j1 : j2;
    const uint32_t sb = smem_u32(smem);
    const int tid = threadIdx.x;
    const int lane = tid & 31, warp = tid >> 5;
    const int wm = warp & 1, wn = warp >> 1;           // warp tile: 64x32
    const int bm = blockIdx.y * 128, bn = blockIdx.x * 128;
    int* ids_s = (int*)(smem + OFF_IDS);

    if (jb.ids && tid < 128) ids_s[tid] = jb.ids[bm + tid];
    if (jb.ids) __syncthreads();

    const int kch = K / 32, nch = 3 * kch;

    // per-thread load coordinates: 512 16B-units per tile, 2 per thread
    const int lrow0 = tid >> 2,        lc0 = tid & 3;        // unit i=0
    const int lrow1 = (tid + 256) >> 2, lc1 = (tid + 256) & 3;

    auto issue = [&](int c) {
        const int p = c / kch;
        const int k0 = (c - p * kch) * 32;
        const __nv_bfloat16* As = (p == 2) ? jb.Al : jb.Ah;
        const __nv_bfloat16* Bs = (p == 1) ? jb.Bl : jb.Bh;
        const uint32_t aoff = sb + ((c & 1) ? OFF_A1 : OFF_A0);
        const uint32_t boff = sb + ((c & 1) ? OFF_B1 : OFF_B0);
        const __nv_bfloat16* a0 = jb.ids ? (As + (size_t)ids_s[lrow0] * K)
                                         : (As + (size_t)(bm + lrow0) * K);
        const __nv_bfloat16* a1 = jb.ids ? (As + (size_t)ids_s[lrow1] * K)
                                         : (As + (size_t)(bm + lrow1) * K);
        cp_async16(aoff + (lrow0 * LDP + lc0 * 8) * 2, a0 + k0 + lc0 * 8);
        cp_async16(aoff + (lrow1 * LDP + lc1 * 8) * 2, a1 + k0 + lc1 * 8);
        cp_async16(boff + (lrow0 * LDP + lc0 * 8) * 2,
                   Bs + (size_t)(bn + lrow0) * K + k0 + lc0 * 8);
        cp_async16(boff + (lrow1 * LDP + lc1 * 8) * 2,
                   Bs + (size_t)(bn + lrow1) * K + k0 + lc1 * 8);
    };

    float acc[4][4][4];
#pragma unroll
    for (int i = 0; i < 4; i++)
#pragma unroll
        for (int j = 0; j < 4; j++)
#pragma unroll
            for (int q = 0; q < 4; q++) acc[i][j][q] = 0.f;

    // ldmatrix per-lane addresses (row part)
    const int arow = lane & 15, acsel = (lane >> 4) * 8;       // A x4
    const int brow = lane & 7,  bcsel = ((lane >> 3) & 1) * 8; // B x2 (lanes 0-15 used)

    issue(0); CP_COMMIT();

    for (int c = 0; c < nch; c++) {
        if (c + 1 < nch) issue(c + 1);
        CP_COMMIT();
        CP_WAIT1();
        __syncthreads();

        const uint32_t aoff = sb + ((c & 1) ? OFF_A1 : OFF_A0);
        const uint32_t boff = sb + ((c & 1) ? OFF_B1 : OFF_B0);
#pragma unroll
        for (int kt = 0; kt < 2; kt++) {
            uint32_t af[4][4], bf[4][2];
#pragma unroll
            for (int mt = 0; mt < 4; mt++)
                ldsm_x4(af[mt], aoff + ((wm * 64 + mt * 16 + arow) * LDP + kt * 16 + acsel) * 2);
#pragma unroll
            for (int nt = 0; nt < 4; nt++)
                ldsm_x2(bf[nt], boff + ((wn * 32 + nt * 8 + brow) * LDP + kt * 16 + bcsel) * 2);
#pragma unroll
            for (int mt = 0; mt < 4; mt++)
#pragma unroll
                for (int nt = 0; nt < 4; nt++)
                    mma16816(acc[mt][nt], af[mt], bf[nt]);
        }
        __syncthreads();
    }

    // epilogue: lane l holds (m = quad, n = 2*pair) pattern
    const int quad = lane >> 2, pair = lane & 3;
#pragma unroll
    for (int mt = 0; mt < 4; mt++) {
#pragma unroll
        for (int h = 0; h < 2; h++) {
            int row = bm + wm * 64 + mt * 16 + quad + h * 8;
            float* crow = jb.C + (size_t)row * N;
#pragma unroll
            for (int nt = 0; nt < 4; nt++) {
                int col = bn + wn * 32 + nt * 8 + pair * 2;
                float v0 = acc[mt][nt][2 * h]     + (jb.bias ? jb.bias[col]     : 0.f);
                float v1 = acc[mt][nt][2 * h + 1] + (jb.bias ? jb.bias[col + 1] : 0.f);
                *(float2*)(crow + col) = make_float2(v0, v1);
                if (jb.Ch) {
                    __nv_bfloat16 h0, l0, h1, l1;
                    split2(v0, h0, l0); split2(v1, h1, l1);
                    *(__nv_bfloat162*)(jb.Ch + (size_t)row * N + col) = __nv_bfloat162(h0, h1);
                    *(__nv_bfloat162*)(jb.Cl + (size_t)row * N + col) = __nv_bfloat162(l0, l1);
                }
            }
        }
    }
}

// ===================== GRU gate update (vectorized) =========================
__device__ __forceinline__ float sigm_(float x) { return 1.f / (1.f + expf(-x)); }

__global__ __launch_bounds__(256)
void gru_update(const float* __restrict__ xg_base, size_t xg_stride,
                const float* __restrict__ inner,
                float* __restrict__ h,
                __nv_bfloat16* __restrict__ hh, __nv_bfloat16* __restrict__ hl,
                const int* __restrict__ tgt, int t,
                __nv_bfloat16* __restrict__ seqh, __nv_bfloat16* __restrict__ seql) {
    int idx = blockIdx.x * 256 + threadIdx.x;     // B*H/4 threads
    int b = idx >> 7;
    int j = (idx & 127) * 4;
    size_t hidx = (size_t)b * HH + j;
    float4 hv = *(float4*)(h + hidx);
    if (tgt[b * TT + t] != 0) {
        const float* xg = xg_base + (size_t)b * xg_stride;
        const float* in = inner + (size_t)b * H3;
        float4 xz = *(const float4*)(xg + j);
        float4 xr = *(const float4*)(xg + HH + j);
        float4 xh = *(const float4*)(xg + 2 * HH + j);
        float4 rz = *(const float4*)(in + j);
        float4 rr = *(const float4*)(in + HH + j);
        float4 rh = *(const float4*)(in + 2 * HH + j);
        float z, r, hg;
        z = sigm_(xz.x + rz.x); r = sigm_(xr.x + rr.x); hg = tanhf(xh.x + r * rh.x); hv.x = z * hv.x + (1.f - z) * hg;
        z = sigm_(xz.y + rz.y); r = sigm_(xr.y + rr.y); hg = tanhf(xh.y + r * rh.y); hv.y = z * hv.y + (1.f - z) * hg;
        z = sigm_(xz.z + rz.z); r = sigm_(xr.z + rr.z); hg = tanhf(xh.z + r * rh.z); hv.z = z * hv.z + (1.f - z) * hg;
        z = sigm_(xz.w + rz.w); r = sigm_(xr.w + rr.w); hg = tanhf(xh.w + r * rh.w); hv.w = z * hv.w + (1.f - z) * hg;
        *(float4*)(h + hidx) = hv;
        __nv_bfloat16 a0,b0,a1,b1,a2,b2,a3,b3;
        split2(hv.x,a0,b0); split2(hv.y,a1,b1); split2(hv.z,a2,b2); split2(hv.w,a3,b3);
        *(__nv_bfloat162*)(hh + hidx)     = __nv_bfloat162(a0,a1);
        *(__nv_bfloat162*)(hh + hidx + 2) = __nv_bfloat162(a2,a3);
        *(__nv_bfloat162*)(hl + hidx)     = __nv_bfloat162(b0,b1);
        *(__nv_bfloat162*)(hl + hidx + 2) = __nv_bfloat162(b2,b3);
    }
    if (seqh) {  // sequence output == state, emitted also on masked steps
        size_t so = (size_t)b * (TT * HH) + j;
        __nv_bfloat16 a0,b0,a1,b1,a2,b2,a3,b3;
        split2(hv.x,a0,b0); split2(hv.y,a1,b1); split2(hv.z,a2,b2); split2(hv.w,a3,b3);
        *(__nv_bfloat162*)(seqh + so)     = __nv_bfloat162(a0,a1);
        *(__nv_bfloat162*)(seqh + so + 2) = __nv_bfloat162(a2,a3);
        *(__nv_bfloat162*)(seql + so)     = __nv_bfloat162(b0,b1);
        *(__nv_bfloat162*)(seql + so + 2) = __nv_bfloat162(b2,b3);
    }
}

// ===================== softmax over V=128 ===================================
__global__ __launch_bounds__(256)
void softmax_kernel(float* __restrict__ out) {
    int row  = blockIdx.x * 8 + (threadIdx.x >> 5);
    int lane = threadIdx.x & 31;
    float* p = out + (size_t)row * VV + lane * 4;
    float4 v = *(float4*)p;
    float m = fmaxf(fmaxf(v.x, v.y), fmaxf(v.z, v.w));
#pragma unroll
    for (int o = 16; o > 0; o >>= 1) m = fmaxf(m, __shfl_xor_sync(0xffffffffu, m, o));
    v.x = expf(v.x - m); v.y = expf(v.y - m); v.z = expf(v.z - m); v.w = expf(v.w - m);
    float s = v.x + v.y + v.z + v.w;
#pragma unroll
    for (int o = 16; o > 0; o >>= 1) s += __shfl_xor_sync(0xffffffffu, s, o);
    float inv = 1.f / s;
    v.x *= inv; v.y *= inv; v.z *= inv; v.w *= inv;
    *(float4*)p = v;
}

// ===================== launch ===============================================
static void* sym(const void* s) { void* p; cudaGetSymbolAddress(&p, s); return p; }

extern "C" void kernel_launch(void* const* d_in, const int* in_sizes, int n_in,
                              void* d_out, int out_size) {
    const int*   tgt = (const int*)  d_in[0];
    const float* enc = (const float*)d_in[1];
    const float* Wi1 = (const float*)d_in[2];
    const float* Wi2 = (const float*)d_in[3];
    const float* emb = (const float*)d_in[4];
    const float* k1  = (const float*)d_in[5];
    const float* rk1 = (const float*)d_in[6];
    const float* b1  = (const float*)d_in[7];
    const float* k2  = (const float*)d_in[8];
    const float* rk2 = (const float*)d_in[9];
    const float* b2  = (const float*)d_in[10];
    const float* Wv  = (const float*)d_in[11];
    const float* bv  = (const float*)d_in[12];
    float* out = (float*)d_out;

    float* x1  = (float*)sym(g_x1);
    float* h1  = (float*)sym(g_h1);   float* h2  = (float*)sym(g_h2);
    float* in1 = (float*)sym(g_in1);  float* xg2 = (float*)sym(g_xg2);  float* in2 = (float*)sym(g_in2);
    __nv_bfloat16 *h1h=(__nv_bfloat16*)sym(g_h1h), *h1l=(__nv_bfloat16*)sym(g_h1l);
    __nv_bfloat16 *h2h=(__nv_bfloat16*)sym(g_h2h), *h2l=(__nv_bfloat16*)sym(g_h2l);
    __nv_bfloat16 *sqh=(__nv_bfloat16*)sym(g_seqh), *sql=(__nv_bfloat16*)sym(g_seql);
    __nv_bfloat16 *ench=(__nv_bfloat16*)sym(g_ench), *encl=(__nv_bfloat16*)sym(g_encl);
    __nv_bfloat16 *k1h=(__nv_bfloat16*)sym(g_k1h),   *k1l=(__nv_bfloat16*)sym(g_k1l);
    __nv_bfloat16 *rk1h=(__nv_bfloat16*)sym(g_rk1h), *rk1l=(__nv_bfloat16*)sym(g_rk1l);
    __nv_bfloat16 *k2h=(__nv_bfloat16*)sym(g_k2h),   *k2l=(__nv_bfloat16*)sym(g_k2l);
    __nv_bfloat16 *rk2h=(__nv_bfloat16*)sym(g_rk2h), *rk2l=(__nv_bfloat16*)sym(g_rk2l);
    __nv_bfloat16 *wi1h=(__nv_bfloat16*)sym(g_wi1h), *wi1l=(__nv_bfloat16*)sym(g_wi1l);
    __nv_bfloat16 *wi2h=(__nv_bfloat16*)sym(g_wi2h), *wi2l=(__nv_bfloat16*)sym(g_wi2l);
    __nv_bfloat16 *wvh=(__nv_bfloat16*)sym(g_wvh),   *wvl=(__nv_bfloat16*)sym(g_wvl);
    __nv_bfloat16 *embh=(__nv_bfloat16*)sym(g_embh), *embl=(__nv_bfloat16*)sym(g_embl);

    dim3 blk(256);

    // ---- prep: transpose + split all weights, split enc/emb ----
    tsplit_kernel<<<dim3(H3/32, EE/32),  blk>>>(k1,  k1h,  k1l,  EE,   H3);
    tsplit_kernel<<<dim3(H3/32, HH/32),  blk>>>(rk1, rk1h, rk1l, HH,   H3);
    tsplit_kernel<<<dim3(H3/32, HH/32),  blk>>>(k2,  k2h,  k2l,  HH,   H3);
    tsplit_kernel<<<dim3(H3/32, HH/32),  blk>>>(rk2, rk2h, rk2l, HH,   H3);
    tsplit_kernel<<<dim3(HH/32, ENCC/32),blk>>>(Wi1, wi1h, wi1l, ENCC, HH);
    tsplit_kernel<<<dim3(HH/32, ENCC/32),blk>>>(Wi2, wi2h, wi2l, ENCC, HH);
    tsplit_kernel<<<dim3(VV/32, HH/32),  blk>>>(Wv,  wvh,  wvl,  HH,   VV);
    split_kernel<<<(VV*EE/4 + 255)/256,   blk>>>(emb, embh, embl, VV*EE/4);
    split_kernel<<<(BB*ENCC/4 + 255)/256, blk>>>(enc, ench, encl, BB*ENCC/4);

    // ---- h0 init: h1 = enc@Wi1, h2 = enc@Wi2 (with bf16 split outputs) ----
    {
        TJob a = {ench, encl, wi1h, wi1l, nullptr, h1, h1h, h1l, nullptr};
        TJob b = {ench, encl, wi2h, wi2l, nullptr, h2, h2h, h2l, nullptr};
        tc_gemm<<<dim3(HH/128, BB/128, 2), blk>>>(a, b, a, ENCC, HH);
    }
    // ---- x1 = gather(emb, tgt) @ k1 + b1[0] ----
    {
        TJob a = {embh, embl, k1h, k1l, b1, x1, nullptr, nullptr, tgt};
        tc_gemm<<<dim3(H3/128, (BB*TT)/128, 1), blk>>>(a, a, a, EE, H3);
    }
    // ---- inner1(t=0) = h1 @ rk1 + b1[1] ----
    {
        TJob a = {h1h, h1l, rk1h, rk1l, b1 + H3, in1, nullptr, nullptr, nullptr};
        tc_gemm<<<dim3(H3/128, BB/128, 1), blk>>>(a, a, a, HH, H3);
    }

    const int gblocks = BB * HH / 4 / 256;  // 1024
    for (int t = 0; t < TT; t++) {
        gru_update<<<gblocks, blk>>>(x1 + (size_t)t * H3, (size_t)TT * H3, in1,
                                     h1, h1h, h1l, tgt, t, nullptr, nullptr);
        {
            TJob a = {h1h, h1l, k2h,  k2l,  b2,      xg2, nullptr, nullptr, nullptr};
            TJob b = {h2h, h2l, rk2h, rk2l, b2 + H3, in2, nullptr, nullptr, nullptr};
            TJob c = {h1h, h1l, rk1h, rk1l, b1 + H3, in1, nullptr, nullptr, nullptr};
            tc_gemm<<<dim3(H3/128, BB/128, 3), blk>>>(a, b, c, HH, H3);
        }
        gru_update<<<gblocks, blk>>>(xg2, (size_t)H3, in2,
                                     h2, h2h, h2l, tgt, t,
                                     sqh + (size_t)t * HH, sql + (size_t)t * HH);
    }

    // ---- logits = seq2 @ Wv + bv, then softmax (in d_out) ----
    {
        TJob a = {sqh, sql, wvh, wvl, bv, out, nullptr, nullptr, nullptr};
        tc_gemm<<<dim3(VV/128, (BB*TT)/128, 1), blk>>>(a, a, a, HH, VV);
    }
    softmax_kernel<<<(BB*TT)/8, blk>>>(out);
}

// round 5
// speedup vs baseline: 2.1390x; 1.0768x over previous
#include <cuda_runtime.h>
#include <cuda_bf16.h>
#include <stdint.h>
#include <math.h>

#define BB   2048
#define TT   48
#define HH   512
#define EE   256
#define VV   128
#define ENCC 1024
#define H3   1536

// ===================== stable-ISA PTX helpers (sm_80+) ======================
__device__ __forceinline__ uint32_t smem_u32(const void* p) {
    uint32_t a;
    asm("{ .reg .u64 t; cvta.to.shared.u64 t, %1; cvt.u32.u64 %0, t; }" : "=r"(a) : "l"(p));
    return a;
}
__device__ __forceinline__ void cp_async16(uint32_t dst, const void* src) {
    asm volatile("cp.async.cg.shared.global [%0], [%1], 16;" :: "r"(dst), "l"(src));
}
#define CP_COMMIT() asm volatile("cp.async.commit_group;" ::: "memory")
#define CP_WAIT1()  asm volatile("cp.async.wait_group 1;" ::: "memory")

__device__ __forceinline__ void ldsm_x4(uint32_t* r, uint32_t addr) {
    asm volatile("ldmatrix.sync.aligned.m8n8.x4.shared.b16 {%0,%1,%2,%3}, [%4];"
                 : "=r"(r[0]), "=r"(r[1]), "=r"(r[2]), "=r"(r[3]) : "r"(addr));
}
__device__ __forceinline__ void ldsm_x2(uint32_t* r, uint32_t addr) {
    asm volatile("ldmatrix.sync.aligned.m8n8.x2.shared.b16 {%0,%1}, [%2];"
                 : "=r"(r[0]), "=r"(r[1]) : "r"(addr));
}
__device__ __forceinline__ void mma16816(float* d, const uint32_t* a, const uint32_t* b) {
    asm volatile("mma.sync.aligned.m16n8k16.row.col.f32.bf16.bf16.f32 "
                 "{%0,%1,%2,%3}, {%4,%5,%6,%7}, {%8,%9}, {%0,%1,%2,%3};"
                 : "+f"(d[0]), "+f"(d[1]), "+f"(d[2]), "+f"(d[3])
                 : "r"(a[0]), "r"(a[1]), "r"(a[2]), "r"(a[3]), "r"(b[0]), "r"(b[1]));
}

// ===================== device scratch (no allocations) ======================
__device__ __align__(16) float g_proj[VV * H3];          // emb@k1 + b1[0], per vocab id
__device__ __align__(16) float g_h1 [BB * HH];
__device__ __align__(16) float g_h2 [BB * HH];
__device__ __align__(16) float g_in1[BB * H3];
__device__ __align__(16) float g_xg2[BB * H3];
__device__ __align__(16) float g_in2[BB * H3];

__device__ __align__(16) __nv_bfloat16 g_h1h[BB * HH], g_h1l[BB * HH];
__device__ __align__(16) __nv_bfloat16 g_h2h[BB * HH], g_h2l[BB * HH];
__device__ __align__(16) __nv_bfloat16 g_seqh[(size_t)BB * TT * HH], g_seql[(size_t)BB * TT * HH];
__device__ __align__(16) __nv_bfloat16 g_ench[BB * ENCC], g_encl[BB * ENCC];

// transposed/split weights: [N,K] row-major, bf16 hi/lo
__device__ __align__(16) __nv_bfloat16 g_k1h [H3 * EE],   g_k1l [H3 * EE];
__device__ __align__(16) __nv_bfloat16 g_rk1h[H3 * HH],   g_rk1l[H3 * HH];
__device__ __align__(16) __nv_bfloat16 g_k2h [H3 * HH],   g_k2l [H3 * HH];
__device__ __align__(16) __nv_bfloat16 g_rk2h[H3 * HH],   g_rk2l[H3 * HH];
__device__ __align__(16) __nv_bfloat16 g_wi1h[HH * ENCC], g_wi1l[HH * ENCC];
__device__ __align__(16) __nv_bfloat16 g_wi2h[HH * ENCC], g_wi2l[HH * ENCC];
__device__ __align__(16) __nv_bfloat16 g_wvh [VV * HH],   g_wvl [VV * HH];
__device__ __align__(16) __nv_bfloat16 g_embh[VV * EE],   g_embl[VV * EE];

__device__ __forceinline__ void split2(float v, __nv_bfloat16& h, __nv_bfloat16& l) {
    h = __float2bfloat16(v);
    l = __float2bfloat16(v - __bfloat162float(h));
}

// ===================== prep: transpose + hi/lo split ========================
__global__ __launch_bounds__(256)
void tsplit_kernel(const float* __restrict__ W, __nv_bfloat16* __restrict__ Th,
                   __nv_bfloat16* __restrict__ Tl, int K, int N) {
    __shared__ float s[32][33];
    int n0 = blockIdx.x * 32, k0 = blockIdx.y * 32;
    int tx = threadIdx.x & 31, ty = threadIdx.x >> 5;
#pragma unroll
    for (int i = 0; i < 32; i += 8)
        s[ty + i][tx] = W[(size_t)(k0 + ty + i) * N + n0 + tx];
    __syncthreads();
#pragma unroll
    for (int i = 0; i < 32; i += 8) {
        float v = s[tx][ty + i];
        __nv_bfloat16 h, l; split2(v, h, l);
        size_t o = (size_t)(n0 + ty + i) * K + k0 + tx;
        Th[o] = h; Tl[o] = l;
    }
}

__global__ __launch_bounds__(256)
void split_kernel(const float* __restrict__ src, __nv_bfloat16* __restrict__ dh,
                  __nv_bfloat16* __restrict__ dl, int n4) {
    int i = blockIdx.x * 256 + threadIdx.x;
    if (i >= n4) return;
    float4 v = ((const float4*)src)[i];
    __nv_bfloat16 h0,l0,h1,l1,h2,l2,h3,l3;
    split2(v.x,h0,l0); split2(v.y,h1,l1); split2(v.z,h2,l2); split2(v.w,h3,l3);
    ((__nv_bfloat162*)dh)[2*i]   = __nv_bfloat162(h0,h1);
    ((__nv_bfloat162*)dh)[2*i+1] = __nv_bfloat162(h2,h3);
    ((__nv_bfloat162*)dl)[2*i]   = __nv_bfloat162(l0,l1);
    ((__nv_bfloat162*)dl)[2*i+1] = __nv_bfloat162(l2,l3);
}

// ===================== mma.sync split-bf16 GEMM =============================
// C[M,N] = A[M,K] @ W[K,N] computed as D[m,n] = sum_k As[m,k] * Bs[n,k]
// with Bs = W^T stored [N,K]. Split: C = Ah*Bh + Ah*Bl + Al*Bh (3 passes).
struct TJob {
    const __nv_bfloat16 *Ah, *Al;   // [M,K]
    const __nv_bfloat16 *Bh, *Bl;   // [N,K]
    const float* bias;              // len N, nullable
    float* C;                       // [M,N]
    __nv_bfloat16 *Ch, *Cl;         // optional split copy of C
};

// tile: BM=128, BN=128, Kc=32. 8 warps, each 64x32. padded rows of 40 bf16.
#define LDP 40
#define OFF_A0  0
#define OFF_B0  (OFF_A0 + 128 * LDP * 2)
#define OFF_A1  (OFF_B0 + 128 * LDP * 2)
#define OFF_B1  (OFF_A1 + 128 * LDP * 2)
#define SMEM_SZ (OFF_B1 + 128 * LDP * 2)

__global__ __launch_bounds__(256, 2)
void tc_gemm(TJob j0, TJob j1, TJob j2, int K, int N) {
    __shared__ __align__(16) char smem[SMEM_SZ];
    const TJob& jb = (blockIdx.z == 0) ? j0 : (blockIdx.z == 1) ? j1 : j2;
    const uint32_t sb = smem_u32(smem);
    const int tid = threadIdx.x;
    const int lane = tid & 31, warp = tid >> 5;
    const int wm = warp & 1, wn = warp >> 1;           // warp tile: 64x32
    const int bm = blockIdx.y * 128, bn = blockIdx.x * 128;

    const int kch = K / 32, nch = 3 * kch;

    // per-thread load coordinates: 512 16B-units per tile, 2 per thread
    const int lrow0 = tid >> 2,         lc0 = tid & 3;
    const int lrow1 = (tid + 256) >> 2, lc1 = (tid + 256) & 3;

    auto issue = [&](int c) {
        const int p = c / kch;
        const int k0 = (c - p * kch) * 32;
        const __nv_bfloat16* As = (p == 2) ? jb.Al : jb.Ah;
        const __nv_bfloat16* Bs = (p == 1) ? jb.Bl : jb.Bh;
        const uint32_t aoff = sb + ((c & 1) ? OFF_A1 : OFF_A0);
        const uint32_t boff = sb + ((c & 1) ? OFF_B1 : OFF_B0);
        cp_async16(aoff + (lrow0 * LDP + lc0 * 8) * 2,
                   As + (size_t)(bm + lrow0) * K + k0 + lc0 * 8);
        cp_async16(aoff + (lrow1 * LDP + lc1 * 8) * 2,
                   As + (size_t)(bm + lrow1) * K + k0 + lc1 * 8);
        cp_async16(boff + (lrow0 * LDP + lc0 * 8) * 2,
                   Bs + (size_t)(bn + lrow0) * K + k0 + lc0 * 8);
        cp_async16(boff + (lrow1 * LDP + lc1 * 8) * 2,
                   Bs + (size_t)(bn + lrow1) * K + k0 + lc1 * 8);
    };

    float acc[4][4][4];
#pragma unroll
    for (int i = 0; i < 4; i++)
#pragma unroll
        for (int j = 0; j < 4; j++)
#pragma unroll
            for (int q = 0; q < 4; q++) acc[i][j][q] = 0.f;

    const int arow = lane & 15, acsel = (lane >> 4) * 8;       // A x4
    const int brow = lane & 7,  bcsel = ((lane >> 3) & 1) * 8; // B x2

    issue(0); CP_COMMIT();

    for (int c = 0; c < nch; c++) {
        if (c + 1 < nch) issue(c + 1);
        CP_COMMIT();
        CP_WAIT1();
        __syncthreads();

        const uint32_t aoff = sb + ((c & 1) ? OFF_A1 : OFF_A0);
        const uint32_t boff = sb + ((c & 1) ? OFF_B1 : OFF_B0);
#pragma unroll
        for (int kt = 0; kt < 2; kt++) {
            uint32_t af[4][4], bf[4][2];
#pragma unroll
            for (int mt = 0; mt < 4; mt++)
                ldsm_x4(af[mt], aoff + ((wm * 64 + mt * 16 + arow) * LDP + kt * 16 + acsel) * 2);
#pragma unroll
            for (int nt = 0; nt < 4; nt++)
                ldsm_x2(bf[nt], boff + ((wn * 32 + nt * 8 + brow) * LDP + kt * 16 + bcsel) * 2);
#pragma unroll
            for (int mt = 0; mt < 4; mt++)
#pragma unroll
                for (int nt = 0; nt < 4; nt++)
                    mma16816(acc[mt][nt], af[mt], bf[nt]);
        }
        __syncthreads();
    }

    const int quad = lane >> 2, pair = lane & 3;
#pragma unroll
    for (int mt = 0; mt < 4; mt++) {
#pragma unroll
        for (int h = 0; h < 2; h++) {
            int row = bm + wm * 64 + mt * 16 + quad + h * 8;
            float* crow = jb.C + (size_t)row * N;
#pragma unroll
            for (int nt = 0; nt < 4; nt++) {
                int col = bn + wn * 32 + nt * 8 + pair * 2;
                float v0 = acc[mt][nt][2 * h]     + (jb.bias ? jb.bias[col]     : 0.f);
                float v1 = acc[mt][nt][2 * h + 1] + (jb.bias ? jb.bias[col + 1] : 0.f);
                *(float2*)(crow + col) = make_float2(v0, v1);
                if (jb.Ch) {
                    __nv_bfloat16 h0, l0, h1, l1;
                    split2(v0, h0, l0); split2(v1, h1, l1);
                    *(__nv_bfloat162*)(jb.Ch + (size_t)row * N + col) = __nv_bfloat162(h0, h1);
                    *(__nv_bfloat162*)(jb.Cl + (size_t)row * N + col) = __nv_bfloat162(l0, l1);
                }
            }
        }
    }
}

// ===================== fused GRU gate update ================================
// Does layer-2 update at time t2 (if >=0) AND layer-1 update at time t1 (if
// >=0 and < TT). Layer-1 x-gates come from the tiny per-vocab proj table.
__device__ __forceinline__ float sigm_(float x) { return 1.f / (1.f + expf(-x)); }

__device__ __forceinline__ void gate4(const float4& xz, const float4& xr, const float4& xh,
                                      const float4& rz, const float4& rr, const float4& rh,
                                      float4& hv) {
    float z, r, hg;
    z = sigm_(xz.x + rz.x); r = sigm_(xr.x + rr.x); hg = tanhf(xh.x + r * rh.x); hv.x = z * hv.x + (1.f - z) * hg;
    z = sigm_(xz.y + rz.y); r = sigm_(xr.y + rr.y); hg = tanhf(xh.y + r * rh.y); hv.y = z * hv.y + (1.f - z) * hg;
    z = sigm_(xz.z + rz.z); r = sigm_(xr.z + rr.z); hg = tanhf(xh.z + r * rh.z); hv.z = z * hv.z + (1.f - z) * hg;
    z = sigm_(xz.w + rz.w); r = sigm_(xr.w + rr.w); hg = tanhf(xh.w + r * rh.w); hv.w = z * hv.w + (1.f - z) * hg;
}
__device__ __forceinline__ void store_split4(const float4& hv, __nv_bfloat16* ph, __nv_bfloat16* pl) {
    __nv_bfloat16 a0,b0,a1,b1,a2,b2,a3,b3;
    split2(hv.x,a0,b0); split2(hv.y,a1,b1); split2(hv.z,a2,b2); split2(hv.w,a3,b3);
    *(__nv_bfloat162*)(ph)     = __nv_bfloat162(a0,a1);
    *(__nv_bfloat162*)(ph + 2) = __nv_bfloat162(a2,a3);
    *(__nv_bfloat162*)(pl)     = __nv_bfloat162(b0,b1);
    *(__nv_bfloat162*)(pl + 2) = __nv_bfloat162(b2,b3);
}

__global__ __launch_bounds__(256)
void gru_step(const float* __restrict__ proj,         // [V,H3] x-gates for layer 1
              const int* __restrict__ tgt,
              int t1,                                  // layer-1 update time (or -1)
              const float* __restrict__ in1, float* __restrict__ h1,
              __nv_bfloat16* __restrict__ h1h, __nv_bfloat16* __restrict__ h1l,
              int t2,                                  // layer-2 update time (or -1)
              const float* __restrict__ xg2, const float* __restrict__ in2,
              float* __restrict__ h2,
              __nv_bfloat16* __restrict__ h2h, __nv_bfloat16* __restrict__ h2l,
              __nv_bfloat16* __restrict__ seqh, __nv_bfloat16* __restrict__ seql) {
    int idx = blockIdx.x * 256 + threadIdx.x;     // B*H/4 threads
    int b = idx >> 7;
    int j = (idx & 127) * 4;
    size_t hidx = (size_t)b * HH + j;

    if (t2 >= 0) {
        float4 hv = *(float4*)(h2 + hidx);
        if (tgt[b * TT + t2] != 0) {
            const float* xg = xg2 + (size_t)b * H3;
            const float* in = in2 + (size_t)b * H3;
            gate4(*(const float4*)(xg + j), *(const float4*)(xg + HH + j), *(const float4*)(xg + 2*HH + j),
                  *(const float4*)(in + j), *(const float4*)(in + HH + j), *(const float4*)(in + 2*HH + j), hv);
            *(float4*)(h2 + hidx) = hv;
            store_split4(hv, h2h + hidx, h2l + hidx);
        }
        size_t so = (size_t)b * (TT * HH) + (size_t)t2 * HH + j;
        store_split4(hv, seqh + so, seql + so);   // output == state, even when masked
    }

    if (t1 >= 0 && t1 < TT) {
        int tok = tgt[b * TT + t1];
        if (tok != 0) {
            float4 hv = *(float4*)(h1 + hidx);
            const float* xg = proj + (size_t)tok * H3;
            const float* in = in1 + (size_t)b * H3;
            gate4(*(const float4*)(xg + j), *(const float4*)(xg + HH + j), *(const float4*)(xg + 2*HH + j),
                  *(const float4*)(in + j), *(const float4*)(in + HH + j), *(const float4*)(in + 2*HH + j), hv);
            *(float4*)(h1 + hidx) = hv;
            store_split4(hv, h1h + hidx, h1l + hidx);
        }
    }
}

// ===================== softmax over V=128 ===================================
__global__ __launch_bounds__(256)
void softmax_kernel(float* __restrict__ out) {
    int row  = blockIdx.x * 8 + (threadIdx.x >> 5);
    int lane = threadIdx.x & 31;
    float* p = out + (size_t)row * VV + lane * 4;
    float4 v = *(float4*)p;
    float m = fmaxf(fmaxf(v.x, v.y), fmaxf(v.z, v.w));
#pragma unroll
    for (int o = 16; o > 0; o >>= 1) m = fmaxf(m, __shfl_xor_sync(0xffffffffu, m, o));
    v.x = expf(v.x - m); v.y = expf(v.y - m); v.z = expf(v.z - m); v.w = expf(v.w - m);
    float s = v.x + v.y + v.z + v.w;
#pragma unroll
    for (int o = 16; o > 0; o >>= 1) s += __shfl_xor_sync(0xffffffffu, s, o);
    float inv = 1.f / s;
    v.x *= inv; v.y *= inv; v.z *= inv; v.w *= inv;
    *(float4*)p = v;
}

// ===================== launch ===============================================
static void* sym(const void* s) { void* p; cudaGetSymbolAddress(&p, s); return p; }

extern "C" void kernel_launch(void* const* d_in, const int* in_sizes, int n_in,
                              void* d_out, int out_size) {
    const int*   tgt = (const int*)  d_in[0];
    const float* enc = (const float*)d_in[1];
    const float* Wi1 = (const float*)d_in[2];
    const float* Wi2 = (const float*)d_in[3];
    const float* emb = (const float*)d_in[4];
    const float* k1  = (const float*)d_in[5];
    const float* rk1 = (const float*)d_in[6];
    const float* b1  = (const float*)d_in[7];
    const float* k2  = (const float*)d_in[8];
    const float* rk2 = (const float*)d_in[9];
    const float* b2  = (const float*)d_in[10];
    const float* Wv  = (const float*)d_in[11];
    const float* bv  = (const float*)d_in[12];
    float* out = (float*)d_out;

    float* proj = (float*)sym(g_proj);
    float* h1  = (float*)sym(g_h1);   float* h2  = (float*)sym(g_h2);
    float* in1 = (float*)sym(g_in1);  float* xg2 = (float*)sym(g_xg2);  float* in2 = (float*)sym(g_in2);
    __nv_bfloat16 *h1h=(__nv_bfloat16*)sym(g_h1h), *h1l=(__nv_bfloat16*)sym(g_h1l);
    __nv_bfloat16 *h2h=(__nv_bfloat16*)sym(g_h2h), *h2l=(__nv_bfloat16*)sym(g_h2l);
    __nv_bfloat16 *sqh=(__nv_bfloat16*)sym(g_seqh), *sql=(__nv_bfloat16*)sym(g_seql);
    __nv_bfloat16 *ench=(__nv_bfloat16*)sym(g_ench), *encl=(__nv_bfloat16*)sym(g_encl);
    __nv_bfloat16 *k1h=(__nv_bfloat16*)sym(g_k1h),   *k1l=(__nv_bfloat16*)sym(g_k1l);
    __nv_bfloat16 *rk1h=(__nv_bfloat16*)sym(g_rk1h), *rk1l=(__nv_bfloat16*)sym(g_rk1l);
    __nv_bfloat16 *k2h=(__nv_bfloat16*)sym(g_k2h),   *k2l=(__nv_bfloat16*)sym(g_k2l);
    __nv_bfloat16 *rk2h=(__nv_bfloat16*)sym(g_rk2h), *rk2l=(__nv_bfloat16*)sym(g_rk2l);
    __nv_bfloat16 *wi1h=(__nv_bfloat16*)sym(g_wi1h), *wi1l=(__nv_bfloat16*)sym(g_wi1l);
    __nv_bfloat16 *wi2h=(__nv_bfloat16*)sym(g_wi2h), *wi2l=(__nv_bfloat16*)sym(g_wi2l);
    __nv_bfloat16 *wvh=(__nv_bfloat16*)sym(g_wvh),   *wvl=(__nv_bfloat16*)sym(g_wvl);
    __nv_bfloat16 *embh=(__nv_bfloat16*)sym(g_embh), *embl=(__nv_bfloat16*)sym(g_embl);

    dim3 blk(256);

    // ---- prep: transpose + split all weights, split enc/emb ----
    tsplit_kernel<<<dim3(H3/32, EE/32),  blk>>>(k1,  k1h,  k1l,  EE,   H3);
    tsplit_kernel<<<dim3(H3/32, HH/32),  blk>>>(rk1, rk1h, rk1l, HH,   H3);
    tsplit_kernel<<<dim3(H3/32, HH/32),  blk>>>(k2,  k2h,  k2l,  HH,   H3);
    tsplit_kernel<<<dim3(H3/32, HH/32),  blk>>>(rk2, rk2h, rk2l, HH,   H3);
    tsplit_kernel<<<dim3(HH/32, ENCC/32),blk>>>(Wi1, wi1h, wi1l, ENCC, HH);
    tsplit_kernel<<<dim3(HH/32, ENCC/32),blk>>>(Wi2, wi2h, wi2l, ENCC, HH);
    tsplit_kernel<<<dim3(VV/32, HH/32),  blk>>>(Wv,  wvh,  wvl,  HH,   VV);
    split_kernel<<<(VV*EE/4 + 255)/256,   blk>>>(emb, embh, embl, VV*EE/4);
    split_kernel<<<(BB*ENCC/4 + 255)/256, blk>>>(enc, ench, encl, BB*ENCC/4);

    // ---- h0 init: h1 = enc@Wi1, h2 = enc@Wi2 (with bf16 split outputs) ----
    {
        TJob a = {ench, encl, wi1h, wi1l, nullptr, h1, h1h, h1l};
        TJob b = {ench, encl, wi2h, wi2l, nullptr, h2, h2h, h2l};
        tc_gemm<<<dim3(HH/128, BB/128, 2), blk>>>(a, b, a, ENCC, HH);
    }
    // ---- proj = emb_table @ k1 + b1[0]  (V=128 rows only!) ----
    {
        TJob a = {embh, embl, k1h, k1l, b1, proj, nullptr, nullptr};
        tc_gemm<<<dim3(H3/128, 1, 1), blk>>>(a, a, a, EE, H3);
    }
    // ---- inner1(t=0) = h1 @ rk1 + b1[1] ----
    {
        TJob a = {h1h, h1l, rk1h, rk1l, b1 + H3, in1, nullptr, nullptr};
        tc_gemm<<<dim3(H3/128, BB/128, 1), blk>>>(a, a, a, HH, H3);
    }
    const int gblocks = BB * HH / 4 / 256;  // 1024
    // layer-1 update for t=0 (no layer-2 work yet)
    gru_step<<<gblocks, blk>>>(proj, tgt, 0, in1, h1, h1h, h1l,
                               -1, nullptr, nullptr, nullptr, nullptr, nullptr,
                               nullptr, nullptr);

    for (int t = 0; t < TT; t++) {
        // fused 3-way GEMM: xg2 = h1@k2+b2[0]; in2 = h2@rk2+b2[1]; in1 = h1@rk1+b1[1] (for t+1)
        {
            TJob a = {h1h, h1l, k2h,  k2l,  b2,      xg2, nullptr, nullptr};
            TJob b = {h2h, h2l, rk2h, rk2l, b2 + H3, in2, nullptr, nullptr};
            TJob c = {h1h, h1l, rk1h, rk1l, b1 + H3, in1, nullptr, nullptr};
            tc_gemm<<<dim3(H3/128, BB/128, 3), blk>>>(a, b, c, HH, H3);
        }
        // fused elementwise: layer-2 update at t (emit seq2[t]) + layer-1 update at t+1
        gru_step<<<gblocks, blk>>>(proj, tgt, t + 1, in1, h1, h1h, h1l,
                                   t, xg2, in2, h2, h2h, h2l, sqh, sql);
    }

    // ---- logits = seq2 @ Wv + bv, then softmax (in d_out) ----
    {
        TJob a = {sqh, sql, wvh, wvl, bv, out, nullptr, nullptr};
        tc_gemm<<<dim3(VV/128, (BB*TT)/128, 1), blk>>>(a, a, a, HH, VV);
    }
    softmax_kernel<<<(BB*TT)/8, blk>>>(out);
}

// round 6
// speedup vs baseline: 2.6607x; 1.2439x over previous
#include <cuda_runtime.h>
#include <cuda_bf16.h>
#include <stdint.h>
#include <math.h>

#define BB   2048
#define TT   48
#define HH   512
#define EE   256
#define VV   128
#define ENCC 1024
#define H3   1536

// ===================== stable-ISA PTX helpers (sm_80+) ======================
__device__ __forceinline__ uint32_t smem_u32(const void* p) {
    uint32_t a;
    asm("{ .reg .u64 t; cvta.to.shared.u64 t, %1; cvt.u32.u64 %0, t; }" : "=r"(a) : "l"(p));
    return a;
}
__device__ __forceinline__ void cp_async16(uint32_t dst, const void* src) {
    asm volatile("cp.async.cg.shared.global [%0], [%1], 16;" :: "r"(dst), "l"(src));
}
#define CP_COMMIT() asm volatile("cp.async.commit_group;" ::: "memory")
#define CP_WAIT1()  asm volatile("cp.async.wait_group 1;" ::: "memory")

__device__ __forceinline__ void ldsm_x4(uint32_t* r, uint32_t addr) {
    asm volatile("ldmatrix.sync.aligned.m8n8.x4.shared.b16 {%0,%1,%2,%3}, [%4];"
                 : "=r"(r[0]), "=r"(r[1]), "=r"(r[2]), "=r"(r[3]) : "r"(addr));
}
__device__ __forceinline__ void ldsm_x2(uint32_t* r, uint32_t addr) {
    asm volatile("ldmatrix.sync.aligned.m8n8.x2.shared.b16 {%0,%1}, [%2];"
                 : "=r"(r[0]), "=r"(r[1]) : "r"(addr));
}
__device__ __forceinline__ void mma16816(float* d, const uint32_t* a, const uint32_t* b) {
    asm volatile("mma.sync.aligned.m16n8k16.row.col.f32.bf16.bf16.f32 "
                 "{%0,%1,%2,%3}, {%4,%5,%6,%7}, {%8,%9}, {%0,%1,%2,%3};"
                 : "+f"(d[0]), "+f"(d[1]), "+f"(d[2]), "+f"(d[3])
                 : "r"(a[0]), "r"(a[1]), "r"(a[2]), "r"(a[3]), "r"(b[0]), "r"(b[1]));
}

// ===================== device scratch (no allocations) ======================
__device__ __align__(16) float g_proj[VV * H3];          // emb@k1 + b1[0], per vocab id
__device__ __align__(16) float g_h1 [BB * HH];
__device__ __align__(16) float g_h2 [BB * HH];
__device__ __align__(16) float g_in1[BB * H3];
__device__ __align__(16) float g_xg2[BB * H3];
__device__ __align__(16) float g_in2[BB * H3];

__device__ __align__(16) __nv_bfloat16 g_h1h[BB * HH], g_h1l[BB * HH];
__device__ __align__(16) __nv_bfloat16 g_h2h[BB * HH], g_h2l[BB * HH];
__device__ __align__(16) __nv_bfloat16 g_seqh[(size_t)BB * TT * HH], g_seql[(size_t)BB * TT * HH];
__device__ __align__(16) __nv_bfloat16 g_ench[BB * ENCC], g_encl[BB * ENCC];

// transposed/split weights: [N,K] row-major, bf16 hi/lo
__device__ __align__(16) __nv_bfloat16 g_k1h [H3 * EE],   g_k1l [H3 * EE];
__device__ __align__(16) __nv_bfloat16 g_rk1h[H3 * HH],   g_rk1l[H3 * HH];
__device__ __align__(16) __nv_bfloat16 g_k2h [H3 * HH],   g_k2l [H3 * HH];
__device__ __align__(16) __nv_bfloat16 g_rk2h[H3 * HH],   g_rk2l[H3 * HH];
__device__ __align__(16) __nv_bfloat16 g_wi1h[HH * ENCC], g_wi1l[HH * ENCC];
__device__ __align__(16) __nv_bfloat16 g_wi2h[HH * ENCC], g_wi2l[HH * ENCC];
__device__ __align__(16) __nv_bfloat16 g_wvh [VV * HH],   g_wvl [VV * HH];
__device__ __align__(16) __nv_bfloat16 g_embh[VV * EE],   g_embl[VV * EE];

__device__ __forceinline__ void split2(float v, __nv_bfloat16& h, __nv_bfloat16& l) {
    h = __float2bfloat16(v);
    l = __float2bfloat16(v - __bfloat162float(h));
}

// ===================== prep: transpose + hi/lo split ========================
__global__ __launch_bounds__(256)
void tsplit_kernel(const float* __restrict__ W, __nv_bfloat16* __restrict__ Th,
                   __nv_bfloat16* __restrict__ Tl, int K, int N) {
    __shared__ float s[32][33];
    int n0 = blockIdx.x * 32, k0 = blockIdx.y * 32;
    int tx = threadIdx.x & 31, ty = threadIdx.x >> 5;
#pragma unroll
    for (int i = 0; i < 32; i += 8)
        s[ty + i][tx] = W[(size_t)(k0 + ty + i) * N + n0 + tx];
    __syncthreads();
#pragma unroll
    for (int i = 0; i < 32; i += 8) {
        float v = s[tx][ty + i];
        __nv_bfloat16 h, l; split2(v, h, l);
        size_t o = (size_t)(n0 + ty + i) * K + k0 + tx;
        Th[o] = h; Tl[o] = l;
    }
}

__global__ __launch_bounds__(256)
void split_kernel(const float* __restrict__ src, __nv_bfloat16* __restrict__ dh,
                  __nv_bfloat16* __restrict__ dl, int n4) {
    int i = blockIdx.x * 256 + threadIdx.x;
    if (i >= n4) return;
    float4 v = ((const float4*)src)[i];
    __nv_bfloat16 h0,l0,h1,l1,h2,l2,h3,l3;
    split2(v.x,h0,l0); split2(v.y,h1,l1); split2(v.z,h2,l2); split2(v.w,h3,l3);
    ((__nv_bfloat162*)dh)[2*i]   = __nv_bfloat162(h0,h1);
    ((__nv_bfloat162*)dh)[2*i+1] = __nv_bfloat162(h2,h3);
    ((__nv_bfloat162*)dl)[2*i]   = __nv_bfloat162(l0,l1);
    ((__nv_bfloat162*)dl)[2*i+1] = __nv_bfloat162(l2,l3);
}

// ===================== mma.sync split-bf16 GEMM (fused passes) ==============
// C = A@W via D[m,n] = sum_k A[m,k]*Bs[n,k], Bs = W^T [N,K].
// Per K-chunk all 4 tiles (Ah,Al,Bh,Bl) are staged once; the three products
// Ah*Bh + Ah*Bl + Al*Bh accumulate into the same fp32 registers.
struct TJob {
    const __nv_bfloat16 *Ah, *Al;   // [M,K]
    const __nv_bfloat16 *Bh, *Bl;   // [N,K]
    const float* bias;              // len N, nullable
    float* C;                       // [M,N]
    __nv_bfloat16 *Ch, *Cl;         // optional split copy of C
};

// tile: BM=128, BN=128, Kc=32. 8 warps, each 64x32. padded rows of 40 bf16.
#define LDP       40
#define TILE_B    (128 * LDP * 2)        // 10240 bytes per operand tile
#define STAGE_B   (4 * TILE_B)           // Ah, Al, Bh, Bl
#define SMEM_DYN  (2 * STAGE_B)          // double buffer = 81920 bytes

__global__ __launch_bounds__(256, 2)
void tc_gemm(TJob j0, TJob j1, TJob j2, int K, int N) {
    extern __shared__ __align__(16) char smem[];
    const TJob& jb = (blockIdx.z == 0) ? j0 : (blockIdx.z == 1) ? j1 : j2;
    const uint32_t sb = smem_u32(smem);
    const int tid = threadIdx.x;
    const int lane = tid & 31, warp = tid >> 5;
    const int wm = warp & 1, wn = warp >> 1;           // warp tile: 64x32
    const int bm = blockIdx.y * 128, bn = blockIdx.x * 128;
    const int kch = K / 32;

    // 4 tiles x 512 16B-units = 2048 units / 256 threads = 8 per thread.
    // unit u = tid + i*256 -> tile = i>>1 (compile-time), w = u&511.
    auto issue = [&](int c) {
        const int k0 = c * 32;
        const uint32_t st = sb + (c & 1) * STAGE_B;
#pragma unroll
        for (int i = 0; i < 8; i++) {
            const int tile = i >> 1;
            const int w = (i & 1) ? (tid + 256) & 511 : tid;
            const int row = w >> 2, c16 = w & 3;
            const __nv_bfloat16* src = (tile == 0) ? jb.Ah : (tile == 1) ? jb.Al
                                     : (tile == 2) ? jb.Bh : jb.Bl;
            const int roff = (tile < 2) ? bm : bn;
            cp_async16(st + tile * TILE_B + (row * LDP + c16 * 8) * 2,
                       src + (size_t)(roff + row) * K + k0 + c16 * 8);
        }
    };

    float acc[4][4][4];
#pragma unroll
    for (int i = 0; i < 4; i++)
#pragma unroll
        for (int j = 0; j < 4; j++)
#pragma unroll
            for (int q = 0; q < 4; q++) acc[i][j][q] = 0.f;

    const int arow = lane & 15, acsel = (lane >> 4) * 8;       // A x4
    const int brow = lane & 7,  bcsel = ((lane >> 3) & 1) * 8; // B x2

    issue(0); CP_COMMIT();

    for (int c = 0; c < kch; c++) {
        if (c + 1 < kch) issue(c + 1);
        CP_COMMIT();
        CP_WAIT1();
        __syncthreads();

        const uint32_t st = sb + (c & 1) * STAGE_B;
        const uint32_t ah = st,              al = st + TILE_B;
        const uint32_t bh = st + 2 * TILE_B, bl = st + 3 * TILE_B;
#pragma unroll
        for (int kt = 0; kt < 2; kt++) {
            uint32_t afh[4][4], bfh[4][2], bfl[4][2];
#pragma unroll
            for (int mt = 0; mt < 4; mt++)
                ldsm_x4(afh[mt], ah + ((wm * 64 + mt * 16 + arow) * LDP + kt * 16 + acsel) * 2);
#pragma unroll
            for (int nt = 0; nt < 4; nt++) {
                ldsm_x2(bfh[nt], bh + ((wn * 32 + nt * 8 + brow) * LDP + kt * 16 + bcsel) * 2);
                ldsm_x2(bfl[nt], bl + ((wn * 32 + nt * 8 + brow) * LDP + kt * 16 + bcsel) * 2);
            }
#pragma unroll
            for (int mt = 0; mt < 4; mt++)
#pragma unroll
                for (int nt = 0; nt < 4; nt++) {
                    mma16816(acc[mt][nt], afh[mt], bfh[nt]);
                    mma16816(acc[mt][nt], afh[mt], bfl[nt]);
                }
            uint32_t afl[4][4];
#pragma unroll
            for (int mt = 0; mt < 4; mt++)
                ldsm_x4(afl[mt], al + ((wm * 64 + mt * 16 + arow) * LDP + kt * 16 + acsel) * 2);
#pragma unroll
            for (int mt = 0; mt < 4; mt++)
#pragma unroll
                for (int nt = 0; nt < 4; nt++)
                    mma16816(acc[mt][nt], afl[mt], bfh[nt]);
        }
        __syncthreads();
    }

    const int quad = lane >> 2, pair = lane & 3;
#pragma unroll
    for (int mt = 0; mt < 4; mt++) {
#pragma unroll
        for (int h = 0; h < 2; h++) {
            int row = bm + wm * 64 + mt * 16 + quad + h * 8;
            float* crow = jb.C + (size_t)row * N;
#pragma unroll
            for (int nt = 0; nt < 4; nt++) {
                int col = bn + wn * 32 + nt * 8 + pair * 2;
                float v0 = acc[mt][nt][2 * h]     + (jb.bias ? jb.bias[col]     : 0.f);
                float v1 = acc[mt][nt][2 * h + 1] + (jb.bias ? jb.bias[col + 1] : 0.f);
                *(float2*)(crow + col) = make_float2(v0, v1);
                if (jb.Ch) {
                    __nv_bfloat16 h0, l0, h1, l1;
                    split2(v0, h0, l0); split2(v1, h1, l1);
                    *(__nv_bfloat162*)(jb.Ch + (size_t)row * N + col) = __nv_bfloat162(h0, h1);
                    *(__nv_bfloat162*)(jb.Cl + (size_t)row * N + col) = __nv_bfloat162(l0, l1);
                }
            }
        }
    }
}

// ===================== fused GRU gate update ================================
__device__ __forceinline__ float sigm_(float x) { return 1.f / (1.f + expf(-x)); }

__device__ __forceinline__ void gate4(const float4& xz, const float4& xr, const float4& xh,
                                      const float4& rz, const float4& rr, const float4& rh,
                                      float4& hv) {
    float z, r, hg;
    z = sigm_(xz.x + rz.x); r = sigm_(xr.x + rr.x); hg = tanhf(xh.x + r * rh.x); hv.x = z * hv.x + (1.f - z) * hg;
    z = sigm_(xz.y + rz.y); r = sigm_(xr.y + rr.y); hg = tanhf(xh.y + r * rh.y); hv.y = z * hv.y + (1.f - z) * hg;
    z = sigm_(xz.z + rz.z); r = sigm_(xr.z + rr.z); hg = tanhf(xh.z + r * rh.z); hv.z = z * hv.z + (1.f - z) * hg;
    z = sigm_(xz.w + rz.w); r = sigm_(xr.w + rr.w); hg = tanhf(xh.w + r * rh.w); hv.w = z * hv.w + (1.f - z) * hg;
}
__device__ __forceinline__ void store_split4(const float4& hv, __nv_bfloat16* ph, __nv_bfloat16* pl) {
    __nv_bfloat16 a0,b0,a1,b1,a2,b2,a3,b3;
    split2(hv.x,a0,b0); split2(hv.y,a1,b1); split2(hv.z,a2,b2); split2(hv.w,a3,b3);
    *(__nv_bfloat162*)(ph)     = __nv_bfloat162(a0,a1);
    *(__nv_bfloat162*)(ph + 2) = __nv_bfloat162(a2,a3);
    *(__nv_bfloat162*)(pl)     = __nv_bfloat162(b0,b1);
    *(__nv_bfloat162*)(pl + 2) = __nv_bfloat162(b2,b3);
}

__global__ __launch_bounds__(256)
void gru_step(const float* __restrict__ proj,         // [V,H3] x-gates for layer 1
              const int* __restrict__ tgt,
              int t1,                                  // layer-1 update time (or -1)
              const float* __restrict__ in1, float* __restrict__ h1,
              __nv_bfloat16* __restrict__ h1h, __nv_bfloat16* __restrict__ h1l,
              int t2,                                  // layer-2 update time (or -1)
              const float* __restrict__ xg2, const float* __restrict__ in2,
              float* __restrict__ h2,
              __nv_bfloat16* __restrict__ h2h, __nv_bfloat16* __restrict__ h2l,
              __nv_bfloat16* __restrict__ seqh, __nv_bfloat16* __restrict__ seql) {
    int idx = blockIdx.x * 256 + threadIdx.x;     // B*H/4 threads
    int b = idx >> 7;
    int j = (idx & 127) * 4;
    size_t hidx = (size_t)b * HH + j;

    if (t2 >= 0) {
        float4 hv = *(float4*)(h2 + hidx);
        if (tgt[b * TT + t2] != 0) {
            const float* xg = xg2 + (size_t)b * H3;
            const float* in = in2 + (size_t)b * H3;
            gate4(*(const float4*)(xg + j), *(const float4*)(xg + HH + j), *(const float4*)(xg + 2*HH + j),
                  *(const float4*)(in + j), *(const float4*)(in + HH + j), *(const float4*)(in + 2*HH + j), hv);
            *(float4*)(h2 + hidx) = hv;
            store_split4(hv, h2h + hidx, h2l + hidx);
        }
        size_t so = (size_t)b * (TT * HH) + (size_t)t2 * HH + j;
        store_split4(hv, seqh + so, seql + so);   // output == state, even when masked
    }

    if (t1 >= 0 && t1 < TT) {
        int tok = tgt[b * TT + t1];
        if (tok != 0) {
            float4 hv = *(float4*)(h1 + hidx);
            const float* xg = proj + (size_t)tok * H3;
            const float* in = in1 + (size_t)b * H3;
            gate4(*(const float4*)(xg + j), *(const float4*)(xg + HH + j), *(const float4*)(xg + 2*HH + j),
                  *(const float4*)(in + j), *(const float4*)(in + HH + j), *(const float4*)(in + 2*HH + j), hv);
            *(float4*)(h1 + hidx) = hv;
            store_split4(hv, h1h + hidx, h1l + hidx);
        }
    }
}

// ===================== softmax over V=128 ===================================
__global__ __launch_bounds__(256)
void softmax_kernel(float* __restrict__ out) {
    int row  = blockIdx.x * 8 + (threadIdx.x >> 5);
    int lane = threadIdx.x & 31;
    float* p = out + (size_t)row * VV + lane * 4;
    float4 v = *(float4*)p;
    float m = fmaxf(fmaxf(v.x, v.y), fmaxf(v.z, v.w));
#pragma unroll
    for (int o = 16; o > 0; o >>= 1) m = fmaxf(m, __shfl_xor_sync(0xffffffffu, m, o));
    v.x = expf(v.x - m); v.y = expf(v.y - m); v.z = expf(v.z - m); v.w = expf(v.w - m);
    float s = v.x + v.y + v.z + v.w;
#pragma unroll
    for (int o = 16; o > 0; o >>= 1) s += __shfl_xor_sync(0xffffffffu, s, o);
    float inv = 1.f / s;
    v.x *= inv; v.y *= inv; v.z *= inv; v.w *= inv;
    *(float4*)p = v;
}

// ===================== launch ===============================================
static void* sym(const void* s) { void* p; cudaGetSymbolAddress(&p, s); return p; }

extern "C" void kernel_launch(void* const* d_in, const int* in_sizes, int n_in,
                              void* d_out, int out_size) {
    const int*   tgt = (const int*)  d_in[0];
    const float* enc = (const float*)d_in[1];
    const float* Wi1 = (const float*)d_in[2];
    const float* Wi2 = (const float*)d_in[3];
    const float* emb = (const float*)d_in[4];
    const float* k1  = (const float*)d_in[5];
    const float* rk1 = (const float*)d_in[6];
    const float* b1  = (const float*)d_in[7];
    const float* k2  = (const float*)d_in[8];
    const float* rk2 = (const float*)d_in[9];
    const float* b2  = (const float*)d_in[10];
    const float* Wv  = (const float*)d_in[11];
    const float* bv  = (const float*)d_in[12];
    float* out = (float*)d_out;

    float* proj = (float*)sym(g_proj);
    float* h1  = (float*)sym(g_h1);   float* h2  = (float*)sym(g_h2);
    float* in1 = (float*)sym(g_in1);  float* xg2 = (float*)sym(g_xg2);  float* in2 = (float*)sym(g_in2);
    __nv_bfloat16 *h1h=(__nv_bfloat16*)sym(g_h1h), *h1l=(__nv_bfloat16*)sym(g_h1l);
    __nv_bfloat16 *h2h=(__nv_bfloat16*)sym(g_h2h), *h2l=(__nv_bfloat16*)sym(g_h2l);
    __nv_bfloat16 *sqh=(__nv_bfloat16*)sym(g_seqh), *sql=(__nv_bfloat16*)sym(g_seql);
    __nv_bfloat16 *ench=(__nv_bfloat16*)sym(g_ench), *encl=(__nv_bfloat16*)sym(g_encl);
    __nv_bfloat16 *k1h=(__nv_bfloat16*)sym(g_k1h),   *k1l=(__nv_bfloat16*)sym(g_k1l);
    __nv_bfloat16 *rk1h=(__nv_bfloat16*)sym(g_rk1h), *rk1l=(__nv_bfloat16*)sym(g_rk1l);
    __nv_bfloat16 *k2h=(__nv_bfloat16*)sym(g_k2h),   *k2l=(__nv_bfloat16*)sym(g_k2l);
    __nv_bfloat16 *rk2h=(__nv_bfloat16*)sym(g_rk2h), *rk2l=(__nv_bfloat16*)sym(g_rk2l);
    __nv_bfloat16 *wi1h=(__nv_bfloat16*)sym(g_wi1h), *wi1l=(__nv_bfloat16*)sym(g_wi1l);
    __nv_bfloat16 *wi2h=(__nv_bfloat16*)sym(g_wi2h), *wi2l=(__nv_bfloat16*)sym(g_wi2l);
    __nv_bfloat16 *wvh=(__nv_bfloat16*)sym(g_wvh),   *wvl=(__nv_bfloat16*)sym(g_wvl);
    __nv_bfloat16 *embh=(__nv_bfloat16*)sym(g_embh), *embl=(__nv_bfloat16*)sym(g_embl);

    cudaFuncSetAttribute(tc_gemm, cudaFuncAttributeMaxDynamicSharedMemorySize, SMEM_DYN);

    dim3 blk(256);

    // ---- prep: transpose + split all weights, split enc/emb ----
    tsplit_kernel<<<dim3(H3/32, EE/32),  blk>>>(k1,  k1h,  k1l,  EE,   H3);
    tsplit_kernel<<<dim3(H3/32, HH/32),  blk>>>(rk1, rk1h, rk1l, HH,   H3);
    tsplit_kernel<<<dim3(H3/32, HH/32),  blk>>>(k2,  k2h,  k2l,  HH,   H3);
    tsplit_kernel<<<dim3(H3/32, HH/32),  blk>>>(rk2, rk2h, rk2l, HH,   H3);
    tsplit_kernel<<<dim3(HH/32, ENCC/32),blk>>>(Wi1, wi1h, wi1l, ENCC, HH);
    tsplit_kernel<<<dim3(HH/32, ENCC/32),blk>>>(Wi2, wi2h, wi2l, ENCC, HH);
    tsplit_kernel<<<dim3(VV/32, HH/32),  blk>>>(Wv,  wvh,  wvl,  HH,   VV);
    split_kernel<<<(VV*EE/4 + 255)/256,   blk>>>(emb, embh, embl, VV*EE/4);
    split_kernel<<<(BB*ENCC/4 + 255)/256, blk>>>(enc, ench, encl, BB*ENCC/4);

    // ---- h0 init: h1 = enc@Wi1, h2 = enc@Wi2 (with bf16 split outputs) ----
    {
        TJob a = {ench, encl, wi1h, wi1l, nullptr, h1, h1h, h1l};
        TJob b = {ench, encl, wi2h, wi2l, nullptr, h2, h2h, h2l};
        tc_gemm<<<dim3(HH/128, BB/128, 2), blk, SMEM_DYN>>>(a, b, a, ENCC, HH);
    }
    // ---- proj = emb_table @ k1 + b1[0]  (V=128 rows only) ----
    {
        TJob a = {embh, embl, k1h, k1l, b1, proj, nullptr, nullptr};
        tc_gemm<<<dim3(H3/128, 1, 1), blk, SMEM_DYN>>>(a, a, a, EE, H3);
    }
    // ---- inner1(t=0) = h1 @ rk1 + b1[1] ----
    {
        TJob a = {h1h, h1l, rk1h, rk1l, b1 + H3, in1, nullptr, nullptr};
        tc_gemm<<<dim3(H3/128, BB/128, 1), blk, SMEM_DYN>>>(a, a, a, HH, H3);
    }
    const int gblocks = BB * HH / 4 / 256;  // 1024
    // layer-1 update for t=0 (no layer-2 work yet)
    gru_step<<<gblocks, blk>>>(proj, tgt, 0, in1, h1, h1h, h1l,
                               -1, nullptr, nullptr, nullptr, nullptr, nullptr,
                               nullptr, nullptr);

    for (int t = 0; t < TT; t++) {
        // fused 3-way GEMM: xg2 = h1@k2+b2[0]; in2 = h2@rk2+b2[1]; in1 = h1@rk1+b1[1] (for t+1)
        {
            TJob a = {h1h, h1l, k2h,  k2l,  b2,      xg2, nullptr, nullptr};
            TJob b = {h2h, h2l, rk2h, rk2l, b2 + H3, in2, nullptr, nullptr};
            TJob c = {h1h, h1l, rk1h, rk1l, b1 + H3, in1, nullptr, nullptr};
            tc_gemm<<<dim3(H3/128, BB/128, 3), blk, SMEM_DYN>>>(a, b, c, HH, H3);
        }
        // fused elementwise: layer-2 update at t (emit seq2[t]) + layer-1 update at t+1
        gru_step<<<gblocks, blk>>>(proj, tgt, t + 1, in1, h1, h1h, h1l,
                                   t, xg2, in2, h2, h2h, h2l, sqh, sql);
    }

    // ---- logits = seq2 @ Wv + bv, then softmax (in d_out) ----
    {
        TJob a = {sqh, sql, wvh, wvl, bv, out, nullptr, nullptr};
        tc_gemm<<<dim3(VV/128, (BB*TT)/128, 1), blk, SMEM_DYN>>>(a, a, a, HH, VV);
    }
    softmax_kernel<<<(BB*TT)/8, blk>>>(out);
}

// round 7
// speedup vs baseline: 2.6810x; 1.0077x over previous
#include <cuda_runtime.h>
#include <cuda_bf16.h>
#include <stdint.h>
#include <math.h>

#define BB   2048
#define TT   48
#define HH   512
#define EE   256
#define VV   128
#define ENCC 1024
#define H3   1536

// ===================== stable-ISA PTX helpers (sm_80+) ======================
__device__ __forceinline__ uint32_t smem_u32(const void* p) {
    uint32_t a;
    asm("{ .reg .u64 t; cvta.to.shared.u64 t, %1; cvt.u32.u64 %0, t; }" : "=r"(a) : "l"(p));
    return a;
}
__device__ __forceinline__ void cp_async16(uint32_t dst, const void* src) {
    asm volatile("cp.async.cg.shared.global [%0], [%1], 16;" :: "r"(dst), "l"(src));
}
#define CP_COMMIT() asm volatile("cp.async.commit_group;" ::: "memory")
#define CP_WAIT1()  asm volatile("cp.async.wait_group 1;" ::: "memory")

__device__ __forceinline__ void ldsm_x4(uint32_t* r, uint32_t addr) {
    asm volatile("ldmatrix.sync.aligned.m8n8.x4.shared.b16 {%0,%1,%2,%3}, [%4];"
                 : "=r"(r[0]), "=r"(r[1]), "=r"(r[2]), "=r"(r[3]) : "r"(addr));
}
__device__ __forceinline__ void ldsm_x2(uint32_t* r, uint32_t addr) {
    asm volatile("ldmatrix.sync.aligned.m8n8.x2.shared.b16 {%0,%1}, [%2];"
                 : "=r"(r[0]), "=r"(r[1]) : "r"(addr));
}
__device__ __forceinline__ void mma16816(float* d, const uint32_t* a, const uint32_t* b) {
    asm volatile("mma.sync.aligned.m16n8k16.row.col.f32.bf16.bf16.f32 "
                 "{%0,%1,%2,%3}, {%4,%5,%6,%7}, {%8,%9}, {%0,%1,%2,%3};"
                 : "+f"(d[0]), "+f"(d[1]), "+f"(d[2]), "+f"(d[3])
                 : "r"(a[0]), "r"(a[1]), "r"(a[2]), "r"(a[3]), "r"(b[0]), "r"(b[1]));
}

// ===================== device scratch (no allocations) ======================
__device__ __align__(16) float g_proj[VV * H3];          // emb@k1 + b1[0], per vocab id
__device__ __align__(16) float g_h1 [BB * HH];
__device__ __align__(16) float g_h2 [BB * HH];
__device__ __align__(16) float g_in1[BB * H3];
__device__ __align__(16) float g_xg2[BB * H3];
__device__ __align__(16) float g_in2[BB * H3];

__device__ __align__(16) __nv_bfloat16 g_h1h[BB * HH], g_h1l[BB * HH];
__device__ __align__(16) __nv_bfloat16 g_h2h[BB * HH], g_h2l[BB * HH];
__device__ __align__(16) __nv_bfloat16 g_seqh[(size_t)BB * TT * HH], g_seql[(size_t)BB * TT * HH];
__device__ __align__(16) __nv_bfloat16 g_ench[BB * ENCC], g_encl[BB * ENCC];

// transposed/split weights: [N,K] row-major, bf16 hi/lo
__device__ __align__(16) __nv_bfloat16 g_k1h [H3 * EE],   g_k1l [H3 * EE];
__device__ __align__(16) __nv_bfloat16 g_rk1h[H3 * HH],   g_rk1l[H3 * HH];
__device__ __align__(16) __nv_bfloat16 g_k2h [H3 * HH],   g_k2l [H3 * HH];
__device__ __align__(16) __nv_bfloat16 g_rk2h[H3 * HH],   g_rk2l[H3 * HH];
__device__ __align__(16) __nv_bfloat16 g_wi1h[HH * ENCC], g_wi1l[HH * ENCC];
__device__ __align__(16) __nv_bfloat16 g_wi2h[HH * ENCC], g_wi2l[HH * ENCC];
__device__ __align__(16) __nv_bfloat16 g_wvh [VV * HH],   g_wvl [VV * HH];
__device__ __align__(16) __nv_bfloat16 g_embh[VV * EE],   g_embl[VV * EE];

__device__ __forceinline__ void split2(float v, __nv_bfloat16& h, __nv_bfloat16& l) {
    h = __float2bfloat16(v);
    l = __float2bfloat16(v - __bfloat162float(h));
}

// ===================== prep: transpose + hi/lo split ========================
__global__ __launch_bounds__(256)
void tsplit_kernel(const float* __restrict__ W, __nv_bfloat16* __restrict__ Th,
                   __nv_bfloat16* __restrict__ Tl, int K, int N) {
    __shared__ float s[32][33];
    int n0 = blockIdx.x * 32, k0 = blockIdx.y * 32;
    int tx = threadIdx.x & 31, ty = threadIdx.x >> 5;
#pragma unroll
    for (int i = 0; i < 32; i += 8)
        s[ty + i][tx] = W[(size_t)(k0 + ty + i) * N + n0 + tx];
    __syncthreads();
#pragma unroll
    for (int i = 0; i < 32; i += 8) {
        float v = s[tx][ty + i];
        __nv_bfloat16 h, l; split2(v, h, l);
        size_t o = (size_t)(n0 + ty + i) * K + k0 + tx;
        Th[o] = h; Tl[o] = l;
    }
}

// z-batched variant: three [HH,H3] weights in one launch
__global__ __launch_bounds__(256)
void tsplit3_kernel(const float* __restrict__ W0, __nv_bfloat16* __restrict__ Th0, __nv_bfloat16* __restrict__ Tl0,
                    const float* __restrict__ W1, __nv_bfloat16* __restrict__ Th1, __nv_bfloat16* __restrict__ Tl1,
                    const float* __restrict__ W2, __nv_bfloat16* __restrict__ Th2, __nv_bfloat16* __restrict__ Tl2) {
    const float* W = (blockIdx.z == 0) ? W0 : (blockIdx.z == 1) ? W1 : W2;
    __nv_bfloat16* Th = (blockIdx.z == 0) ? Th0 : (blockIdx.z == 1) ? Th1 : Th2;
    __nv_bfloat16* Tl = (blockIdx.z == 0) ? Tl0 : (blockIdx.z == 1) ? Tl1 : Tl2;
    const int K = HH, N = H3;
    __shared__ float s[32][33];
    int n0 = blockIdx.x * 32, k0 = blockIdx.y * 32;
    int tx = threadIdx.x & 31, ty = threadIdx.x >> 5;
#pragma unroll
    for (int i = 0; i < 32; i += 8)
        s[ty + i][tx] = W[(size_t)(k0 + ty + i) * N + n0 + tx];
    __syncthreads();
#pragma unroll
    for (int i = 0; i < 32; i += 8) {
        float v = s[tx][ty + i];
        __nv_bfloat16 h, l; split2(v, h, l);
        size_t o = (size_t)(n0 + ty + i) * K + k0 + tx;
        Th[o] = h; Tl[o] = l;
    }
}

__global__ __launch_bounds__(256)
void split_kernel(const float* __restrict__ src, __nv_bfloat16* __restrict__ dh,
                  __nv_bfloat16* __restrict__ dl, int n4) {
    int i = blockIdx.x * 256 + threadIdx.x;
    if (i >= n4) return;
    float4 v = ((const float4*)src)[i];
    __nv_bfloat16 h0,l0,h1,l1,h2,l2,h3,l3;
    split2(v.x,h0,l0); split2(v.y,h1,l1); split2(v.z,h2,l2); split2(v.w,h3,l3);
    ((__nv_bfloat162*)dh)[2*i]   = __nv_bfloat162(h0,h1);
    ((__nv_bfloat162*)dh)[2*i+1] = __nv_bfloat162(h2,h3);
    ((__nv_bfloat162*)dl)[2*i]   = __nv_bfloat162(l0,l1);
    ((__nv_bfloat162*)dl)[2*i+1] = __nv_bfloat162(l2,l3);
}

// ===================== mma.sync split-bf16 GEMM (fused passes) ==============
// C = A@W via D[m,n] = sum_k A[m,k]*Bs[n,k], Bs = W^T [N,K].
// Per K-chunk all 4 tiles (Ah,Al,Bh,Bl) are staged once; the three products
// Ah*Bh + Ah*Bl + Al*Bh accumulate into the same fp32 registers.
struct TJob {
    const __nv_bfloat16 *Ah, *Al;   // [M,K]
    const __nv_bfloat16 *Bh, *Bl;   // [N,K]
    const float* bias;              // len N, nullable
    float* C;                       // [M,N]
    __nv_bfloat16 *Ch, *Cl;         // optional split copy of C
};

// tile: BM=128, BN=128, Kc=32. 8 warps, each 64x32. padded rows of 40 bf16.
#define LDP       40
#define TILE_B    (128 * LDP * 2)        // 10240 bytes per operand tile
#define STAGE_B   (4 * TILE_B)           // Ah, Al, Bh, Bl
#define SMEM_DYN  (2 * STAGE_B)          // double buffer = 81920 bytes

__global__ __launch_bounds__(256, 2)
void tc_gemm(TJob j0, TJob j1, TJob j2, int K, int N) {
    extern __shared__ __align__(16) char smem[];
    const TJob& jb = (blockIdx.z == 0) ? j0 : (blockIdx.z == 1) ? j1 : j2;
    const uint32_t sb = smem_u32(smem);
    const int tid = threadIdx.x;
    const int lane = tid & 31, warp = tid >> 5;
    const int wm = warp & 1, wn = warp >> 1;           // warp tile: 64x32
    const int bm = blockIdx.y * 128, bn = blockIdx.x * 128;
    const int kch = K / 32;

    auto issue = [&](int c) {
        const int k0 = c * 32;
        const uint32_t st = sb + (c & 1) * STAGE_B;
#pragma unroll
        for (int i = 0; i < 8; i++) {
            const int tile = i >> 1;
            const int w = (i & 1) ? (tid + 256) & 511 : tid;
            const int row = w >> 2, c16 = w & 3;
            const __nv_bfloat16* src = (tile == 0) ? jb.Ah : (tile == 1) ? jb.Al
                                     : (tile == 2) ? jb.Bh : jb.Bl;
            const int roff = (tile < 2) ? bm : bn;
            cp_async16(st + tile * TILE_B + (row * LDP + c16 * 8) * 2,
                       src + (size_t)(roff + row) * K + k0 + c16 * 8);
        }
    };

    float acc[4][4][4];
#pragma unroll
    for (int i = 0; i < 4; i++)
#pragma unroll
        for (int j = 0; j < 4; j++)
#pragma unroll
            for (int q = 0; q < 4; q++) acc[i][j][q] = 0.f;

    const int arow = lane & 15, acsel = (lane >> 4) * 8;       // A x4
    const int brow = lane & 7,  bcsel = ((lane >> 3) & 1) * 8; // B x2

    issue(0); CP_COMMIT();

    for (int c = 0; c < kch; c++) {
        if (c + 1 < kch) issue(c + 1);
        CP_COMMIT();
        CP_WAIT1();
        __syncthreads();

        const uint32_t st = sb + (c & 1) * STAGE_B;
        const uint32_t ah = st,              al = st + TILE_B;
        const uint32_t bh = st + 2 * TILE_B, bl = st + 3 * TILE_B;
#pragma unroll
        for (int kt = 0; kt < 2; kt++) {
            uint32_t afh[4][4], bfh[4][2], bfl[4][2];
#pragma unroll
            for (int mt = 0; mt < 4; mt++)
                ldsm_x4(afh[mt], ah + ((wm * 64 + mt * 16 + arow) * LDP + kt * 16 + acsel) * 2);
#pragma unroll
            for (int nt = 0; nt < 4; nt++) {
                ldsm_x2(bfh[nt], bh + ((wn * 32 + nt * 8 + brow) * LDP + kt * 16 + bcsel) * 2);
                ldsm_x2(bfl[nt], bl + ((wn * 32 + nt * 8 + brow) * LDP + kt * 16 + bcsel) * 2);
            }
#pragma unroll
            for (int mt = 0; mt < 4; mt++)
#pragma unroll
                for (int nt = 0; nt < 4; nt++) {
                    mma16816(acc[mt][nt], afh[mt], bfh[nt]);
                    mma16816(acc[mt][nt], afh[mt], bfl[nt]);
                }
            uint32_t afl[4][4];
#pragma unroll
            for (int mt = 0; mt < 4; mt++)
                ldsm_x4(afl[mt], al + ((wm * 64 + mt * 16 + arow) * LDP + kt * 16 + acsel) * 2);
#pragma unroll
            for (int mt = 0; mt < 4; mt++)
#pragma unroll
                for (int nt = 0; nt < 4; nt++)
                    mma16816(acc[mt][nt], afl[mt], bfh[nt]);
        }
        __syncthreads();
    }

    const int quad = lane >> 2, pair = lane & 3;
#pragma unroll
    for (int mt = 0; mt < 4; mt++) {
#pragma unroll
        for (int h = 0; h < 2; h++) {
            int row = bm + wm * 64 + mt * 16 + quad + h * 8;
            float* crow = jb.C + (size_t)row * N;
#pragma unroll
            for (int nt = 0; nt < 4; nt++) {
                int col = bn + wn * 32 + nt * 8 + pair * 2;
                float v0 = acc[mt][nt][2 * h]     + (jb.bias ? jb.bias[col]     : 0.f);
                float v1 = acc[mt][nt][2 * h + 1] + (jb.bias ? jb.bias[col + 1] : 0.f);
                *(float2*)(crow + col) = make_float2(v0, v1);
                if (jb.Ch) {
                    __nv_bfloat16 h0, l0, h1, l1;
                    split2(v0, h0, l0); split2(v1, h1, l1);
                    *(__nv_bfloat162*)(jb.Ch + (size_t)row * N + col) = __nv_bfloat162(h0, h1);
                    *(__nv_bfloat162*)(jb.Cl + (size_t)row * N + col) = __nv_bfloat162(l0, l1);
                }
            }
        }
    }
}

// ===================== fused GRU gate update ================================
__device__ __forceinline__ float sigm_(float x) { return 1.f / (1.f + expf(-x)); }

__device__ __forceinline__ void gate4(const float4& xz, const float4& xr, const float4& xh,
                                      const float4& rz, const float4& rr, const float4& rh,
                                      float4& hv) {
    float z, r, hg;
    z = sigm_(xz.x + rz.x); r = sigm_(xr.x + rr.x); hg = tanhf(xh.x + r * rh.x); hv.x = z * hv.x + (1.f - z) * hg;
    z = sigm_(xz.y + rz.y); r = sigm_(xr.y + rr.y); hg = tanhf(xh.y + r * rh.y); hv.y = z * hv.y + (1.f - z) * hg;
    z = sigm_(xz.z + rz.z); r = sigm_(xr.z + rr.z); hg = tanhf(xh.z + r * rh.z); hv.z = z * hv.z + (1.f - z) * hg;
    z = sigm_(xz.w + rz.w); r = sigm_(xr.w + rr.w); hg = tanhf(xh.w + r * rh.w); hv.w = z * hv.w + (1.f - z) * hg;
}
__device__ __forceinline__ void store_split4(const float4& hv, __nv_bfloat16* ph, __nv_bfloat16* pl) {
    __nv_bfloat16 a0,b0,a1,b1,a2,b2,a3,b3;
    split2(hv.x,a0,b0); split2(hv.y,a1,b1); split2(hv.z,a2,b2); split2(hv.w,a3,b3);
    *(__nv_bfloat162*)(ph)     = __nv_bfloat162(a0,a1);
    *(__nv_bfloat162*)(ph + 2) = __nv_bfloat162(a2,a3);
    *(__nv_bfloat162*)(pl)     = __nv_bfloat162(b0,b1);
    *(__nv_bfloat162*)(pl + 2) = __nv_bfloat162(b2,b3);
}

__global__ __launch_bounds__(256)
void gru_step(const float* __restrict__ proj,         // [V,H3] x-gates for layer 1
              const int* __restrict__ tgt,
              int t1,                                  // layer-1 update time (or -1)
              const float* __restrict__ in1, float* __restrict__ h1,
              __nv_bfloat16* __restrict__ h1h, __nv_bfloat16* __restrict__ h1l,
              int t2,                                  // layer-2 update time (or -1)
              const float* __restrict__ xg2, const float* __restrict__ in2,
              float* __restrict__ h2,
              __nv_bfloat16* __restrict__ h2h, __nv_bfloat16* __restrict__ h2l,
              __nv_bfloat16* __restrict__ seqh, __nv_bfloat16* __restrict__ seql) {
    int idx = blockIdx.x * 256 + threadIdx.x;     // B*H/4 threads
    int b = idx >> 7;
    int j = (idx & 127) * 4;
    size_t hidx = (size_t)b * HH + j;

    if (t2 >= 0) {
        float4 hv = *(float4*)(h2 + hidx);
        if (tgt[b * TT + t2] != 0) {
            const float* xg = xg2 + (size_t)b * H3;
            const float* in = in2 + (size_t)b * H3;
            gate4(*(const float4*)(xg + j), *(const float4*)(xg + HH + j), *(const float4*)(xg + 2*HH + j),
                  *(const float4*)(in + j), *(const float4*)(in + HH + j), *(const float4*)(in + 2*HH + j), hv);
            *(float4*)(h2 + hidx) = hv;
            store_split4(hv, h2h + hidx, h2l + hidx);
        }
        size_t so = (size_t)b * (TT * HH) + (size_t)t2 * HH + j;
        store_split4(hv, seqh + so, seql + so);   // output == state, even when masked
    }

    if (t1 >= 0 && t1 < TT) {
        int tok = tgt[b * TT + t1];
        if (tok != 0) {
            float4 hv = *(float4*)(h1 + hidx);
            const float* xg = proj + (size_t)tok * H3;
            const float* in = in1 + (size_t)b * H3;
            gate4(*(const float4*)(xg + j), *(const float4*)(xg + HH + j), *(const float4*)(xg + 2*HH + j),
                  *(const float4*)(in + j), *(const float4*)(in + HH + j), *(const float4*)(in + 2*HH + j), hv);
            *(float4*)(h1 + hidx) = hv;
            store_split4(hv, h1h + hidx, h1l + hidx);
        }
    }
}

// ===================== softmax over V=128 ===================================
__global__ __launch_bounds__(256)
void softmax_kernel(float* __restrict__ out) {
    int row  = blockIdx.x * 8 + (threadIdx.x >> 5);
    int lane = threadIdx.x & 31;
    float* p = out + (size_t)row * VV + lane * 4;
    float4 v = *(float4*)p;
    float m = fmaxf(fmaxf(v.x, v.y), fmaxf(v.z, v.w));
#pragma unroll
    for (int o = 16; o > 0; o >>= 1) m = fmaxf(m, __shfl_xor_sync(0xffffffffu, m, o));
    v.x = expf(v.x - m); v.y = expf(v.y - m); v.z = expf(v.z - m); v.w = expf(v.w - m);
    float s = v.x + v.y + v.z + v.w;
#pragma unroll
    for (int o = 16; o > 0; o >>= 1) s += __shfl_xor_sync(0xffffffffu, s, o);
    float inv = 1.f / s;
    v.x *= inv; v.y *= inv; v.z *= inv; v.w *= inv;
    *(float4*)p = v;
}

// ===================== launch ===============================================
static void* sym(const void* s) { void* p; cudaGetSymbolAddress(&p, s); return p; }

extern "C" void kernel_launch(void* const* d_in, const int* in_sizes, int n_in,
                              void* d_out, int out_size) {
    const int*   tgt = (const int*)  d_in[0];
    const float* enc = (const float*)d_in[1];
    const float* Wi1 = (const float*)d_in[2];
    const float* Wi2 = (const float*)d_in[3];
    const float* emb = (const float*)d_in[4];
    const float* k1  = (const float*)d_in[5];
    const float* rk1 = (const float*)d_in[6];
    const float* b1  = (const float*)d_in[7];
    const float* k2  = (const float*)d_in[8];
    const float* rk2 = (const float*)d_in[9];
    const float* b2  = (const float*)d_in[10];
    const float* Wv  = (const float*)d_in[11];
    const float* bv  = (const float*)d_in[12];
    float* out = (float*)d_out;

    float* proj = (float*)sym(g_proj);
    float* h1  = (float*)sym(g_h1);   float* h2  = (float*)sym(g_h2);
    float* in1 = (float*)sym(g_in1);  float* xg2 = (float*)sym(g_xg2);  float* in2 = (float*)sym(g_in2);
    __nv_bfloat16 *h1h=(__nv_bfloat16*)sym(g_h1h), *h1l=(__nv_bfloat16*)sym(g_h1l);
    __nv_bfloat16 *h2h=(__nv_bfloat16*)sym(g_h2h), *h2l=(__nv_bfloat16*)sym(g_h2l);
    __nv_bfloat16 *sqh=(__nv_bfloat16*)sym(g_seqh), *sql=(__nv_bfloat16*)sym(g_seql);
    __nv_bfloat16 *ench=(__nv_bfloat16*)sym(g_ench), *encl=(__nv_bfloat16*)sym(g_encl);
    __nv_bfloat16 *k1h=(__nv_bfloat16*)sym(g_k1h),   *k1l=(__nv_bfloat16*)sym(g_k1l);
    __nv_bfloat16 *rk1h=(__nv_bfloat16*)sym(g_rk1h), *rk1l=(__nv_bfloat16*)sym(g_rk1l);
    __nv_bfloat16 *k2h=(__nv_bfloat16*)sym(g_k2h),   *k2l=(__nv_bfloat16*)sym(g_k2l);
    __nv_bfloat16 *rk2h=(__nv_bfloat16*)sym(g_rk2h), *rk2l=(__nv_bfloat16*)sym(g_rk2l);
    __nv_bfloat16 *wi1h=(__nv_bfloat16*)sym(g_wi1h), *wi1l=(__nv_bfloat16*)sym(g_wi1l);
    __nv_bfloat16 *wi2h=(__nv_bfloat16*)sym(g_wi2h), *wi2l=(__nv_bfloat16*)sym(g_wi2l);
    __nv_bfloat16 *wvh=(__nv_bfloat16*)sym(g_wvh),   *wvl=(__nv_bfloat16*)sym(g_wvl);
    __nv_bfloat16 *embh=(__nv_bfloat16*)sym(g_embh), *embl=(__nv_bfloat16*)sym(g_embl);

    cudaFuncSetAttribute(tc_gemm, cudaFuncAttributeMaxDynamicSharedMemorySize, SMEM_DYN);

    dim3 blk(256);

    // ---- prep, ordered so that the 6th launch is a tc_gemm (ncu -s 5 -c 1 tap) ----
    tsplit_kernel<<<dim3(HH/32, ENCC/32),blk>>>(Wi1, wi1h, wi1l, ENCC, HH);          // 1
    tsplit_kernel<<<dim3(HH/32, ENCC/32),blk>>>(Wi2, wi2h, wi2l, ENCC, HH);          // 2
    split_kernel<<<(BB*ENCC/4 + 255)/256, blk>>>(enc, ench, encl, BB*ENCC/4);        // 3
    tsplit_kernel<<<dim3(H3/32, EE/32),  blk>>>(k1,  k1h,  k1l,  EE,   H3);          // 4
    split_kernel<<<(VV*EE/4 + 255)/256,   blk>>>(emb, embh, embl, VV*EE/4);          // 5

    // 6: h0 init GEMM — profiled launch
    {
        TJob a = {ench, encl, wi1h, wi1l, nullptr, h1, h1h, h1l};
        TJob b = {ench, encl, wi2h, wi2l, nullptr, h2, h2h, h2l};
        tc_gemm<<<dim3(HH/128, BB/128, 2), blk, SMEM_DYN>>>(a, b, a, ENCC, HH);
    }

    // remaining prep
    tsplit3_kernel<<<dim3(H3/32, HH/32, 3), blk>>>(rk1, rk1h, rk1l,
                                                   k2,  k2h,  k2l,
                                                   rk2, rk2h, rk2l);
    tsplit_kernel<<<dim3(VV/32, HH/32),  blk>>>(Wv,  wvh,  wvl,  HH,   VV);

    // proj = emb_table @ k1 + b1[0]  (V=128 rows only)
    {
        TJob a = {embh, embl, k1h, k1l, b1, proj, nullptr, nullptr};
        tc_gemm<<<dim3(H3/128, 1, 1), blk, SMEM_DYN>>>(a, a, a, EE, H3);
    }
    // inner1(t=0) = h1 @ rk1 + b1[1]
    {
        TJob a = {h1h, h1l, rk1h, rk1l, b1 + H3, in1, nullptr, nullptr};
        tc_gemm<<<dim3(H3/128, BB/128, 1), blk, SMEM_DYN>>>(a, a, a, HH, H3);
    }
    const int gblocks = BB * HH / 4 / 256;  // 1024
    // layer-1 update for t=0
    gru_step<<<gblocks, blk>>>(proj, tgt, 0, in1, h1, h1h, h1l,
                               -1, nullptr, nullptr, nullptr, nullptr, nullptr,
                               nullptr, nullptr);

    for (int t = 0; t < TT; t++) {
        // fused GEMM: xg2 = h1@k2+b2[0]; in2 = h2@rk2+b2[1]; in1 = h1@rk1+b1[1] (skip at last t)
        {
            TJob a = {h1h, h1l, k2h,  k2l,  b2,      xg2, nullptr, nullptr};
            TJob b = {h2h, h2l, rk2h, rk2l, b2 + H3, in2, nullptr, nullptr};
            TJob c = {h1h, h1l, rk1h, rk1l, b1 + H3, in1, nullptr, nullptr};
            int nz = (t == TT - 1) ? 2 : 3;   // in1 for t=TT is never consumed
            tc_gemm<<<dim3(H3/128, BB/128, nz), blk, SMEM_DYN>>>(a, b, c, HH, H3);
        }
        // fused elementwise: layer-2 update at t (emit seq2[t]) + layer-1 update at t+1
        gru_step<<<gblocks, blk>>>(proj, tgt, t + 1, in1, h1, h1h, h1l,
                                   t, xg2, in2, h2, h2h, h2l, sqh, sql);
    }

    // ---- logits = seq2 @ Wv + bv, then softmax (in d_out) ----
    {
        TJob a = {sqh, sql, wvh, wvl, bv, out, nullptr, nullptr};
        tc_gemm<<<dim3(VV/128, (BB*TT)/128, 1), blk, SMEM_DYN>>>(a, a, a, HH, VV);
    }
    softmax_kernel<<<(BB*TT)/8, blk>>>(out);
}

// round 8
// speedup vs baseline: 2.7433x; 1.0232x over previous
#include <cuda_runtime.h>
#include <cuda_bf16.h>
#include <stdint.h>
#include <math.h>

#define BB   2048
#define TT   48
#define HH   512
#define EE   256
#define VV   128
#define ENCC 1024
#define H3   1536

// ===================== stable-ISA PTX helpers (sm_80+) ======================
__device__ __forceinline__ uint32_t smem_u32(const void* p) {
    uint32_t a;
    asm("{ .reg .u64 t; cvta.to.shared.u64 t, %1; cvt.u32.u64 %0, t; }" : "=r"(a) : "l"(p));
    return a;
}
__device__ __forceinline__ void cp_async16(uint32_t dst, const void* src) {
    asm volatile("cp.async.cg.shared.global [%0], [%1], 16;" :: "r"(dst), "l"(src));
}
#define CP_COMMIT() asm volatile("cp.async.commit_group;" ::: "memory")
#define CP_WAIT1()  asm volatile("cp.async.wait_group 1;" ::: "memory")

__device__ __forceinline__ void ldsm_x4(uint32_t* r, uint32_t addr) {
    asm volatile("ldmatrix.sync.aligned.m8n8.x4.shared.b16 {%0,%1,%2,%3}, [%4];"
                 : "=r"(r[0]), "=r"(r[1]), "=r"(r[2]), "=r"(r[3]) : "r"(addr));
}
__device__ __forceinline__ void mma16816(float* d, const uint32_t* a, const uint32_t* b) {
    asm volatile("mma.sync.aligned.m16n8k16.row.col.f32.bf16.bf16.f32 "
                 "{%0,%1,%2,%3}, {%4,%5,%6,%7}, {%8,%9}, {%0,%1,%2,%3};"
                 : "+f"(d[0]), "+f"(d[1]), "+f"(d[2]), "+f"(d[3])
                 : "r"(a[0]), "r"(a[1]), "r"(a[2]), "r"(a[3]), "r"(b[0]), "r"(b[1]));
}

// ===================== device scratch (no allocations) ======================
__device__ __align__(16) float g_proj[VV * H3];          // emb@k1 + b1[0], per vocab id
__device__ __align__(16) float g_h1 [BB * HH];
__device__ __align__(16) float g_h2 [BB * HH];
__device__ __align__(16) float g_in1[BB * H3];
__device__ __align__(16) float g_xg2[BB * H3];
__device__ __align__(16) float g_in2[BB * H3];

__device__ __align__(16) __nv_bfloat16 g_h1h[BB * HH], g_h1l[BB * HH];
__device__ __align__(16) __nv_bfloat16 g_h2h[BB * HH], g_h2l[BB * HH];
__device__ __align__(16) __nv_bfloat16 g_seqh[(size_t)BB * TT * HH], g_seql[(size_t)BB * TT * HH];
__device__ __align__(16) __nv_bfloat16 g_ench[BB * ENCC], g_encl[BB * ENCC];

// transposed/split weights: [N,K] row-major, bf16 hi/lo
__device__ __align__(16) __nv_bfloat16 g_k1h [H3 * EE],   g_k1l [H3 * EE];
__device__ __align__(16) __nv_bfloat16 g_rk1h[H3 * HH],   g_rk1l[H3 * HH];
__device__ __align__(16) __nv_bfloat16 g_k2h [H3 * HH],   g_k2l [H3 * HH];
__device__ __align__(16) __nv_bfloat16 g_rk2h[H3 * HH],   g_rk2l[H3 * HH];
__device__ __align__(16) __nv_bfloat16 g_wi1h[HH * ENCC], g_wi1l[HH * ENCC];
__device__ __align__(16) __nv_bfloat16 g_wi2h[HH * ENCC], g_wi2l[HH * ENCC];
__device__ __align__(16) __nv_bfloat16 g_wvh [VV * HH],   g_wvl [VV * HH];
__device__ __align__(16) __nv_bfloat16 g_embh[VV * EE],   g_embl[VV * EE];

__device__ __forceinline__ void split2(float v, __nv_bfloat16& h, __nv_bfloat16& l) {
    h = __float2bfloat16(v);
    l = __float2bfloat16(v - __bfloat162float(h));
}

// ===================== prep: transpose + hi/lo split ========================
__global__ __launch_bounds__(256)
void tsplit_kernel(const float* __restrict__ W, __nv_bfloat16* __restrict__ Th,
                   __nv_bfloat16* __restrict__ Tl, int K, int N) {
    __shared__ float s[32][33];
    int n0 = blockIdx.x * 32, k0 = blockIdx.y * 32;
    int tx = threadIdx.x & 31, ty = threadIdx.x >> 5;
#pragma unroll
    for (int i = 0; i < 32; i += 8)
        s[ty + i][tx] = W[(size_t)(k0 + ty + i) * N + n0 + tx];
    __syncthreads();
#pragma unroll
    for (int i = 0; i < 32; i += 8) {
        float v = s[tx][ty + i];
        __nv_bfloat16 h, l; split2(v, h, l);
        size_t o = (size_t)(n0 + ty + i) * K + k0 + tx;
        Th[o] = h; Tl[o] = l;
    }
}

// z-batched variant: three [HH,H3] weights in one launch
__global__ __launch_bounds__(256)
void tsplit3_kernel(const float* __restrict__ W0, __nv_bfloat16* __restrict__ Th0, __nv_bfloat16* __restrict__ Tl0,
                    const float* __restrict__ W1, __nv_bfloat16* __restrict__ Th1, __nv_bfloat16* __restrict__ Tl1,
                    const float* __restrict__ W2, __nv_bfloat16* __restrict__ Th2, __nv_bfloat16* __restrict__ Tl2) {
    const float* W = (blockIdx.z == 0) ? W0 : (blockIdx.z == 1) ? W1 : W2;
    __nv_bfloat16* Th = (blockIdx.z == 0) ? Th0 : (blockIdx.z == 1) ? Th1 : Th2;
    __nv_bfloat16* Tl = (blockIdx.z == 0) ? Tl0 : (blockIdx.z == 1) ? Tl1 : Tl2;
    const int K = HH, N = H3;
    __shared__ float s[32][33];
    int n0 = blockIdx.x * 32, k0 = blockIdx.y * 32;
    int tx = threadIdx.x & 31, ty = threadIdx.x >> 5;
#pragma unroll
    for (int i = 0; i < 32; i += 8)
        s[ty + i][tx] = W[(size_t)(k0 + ty + i) * N + n0 + tx];
    __syncthreads();
#pragma unroll
    for (int i = 0; i < 32; i += 8) {
        float v = s[tx][ty + i];
        __nv_bfloat16 h, l; split2(v, h, l);
        size_t o = (size_t)(n0 + ty + i) * K + k0 + tx;
        Th[o] = h; Tl[o] = l;
    }
}

__global__ __launch_bounds__(256)
void split_kernel(const float* __restrict__ src, __nv_bfloat16* __restrict__ dh,
                  __nv_bfloat16* __restrict__ dl, int n4) {
    int i = blockIdx.x * 256 + threadIdx.x;
    if (i >= n4) return;
    float4 v = ((const float4*)src)[i];
    __nv_bfloat16 h0,l0,h1,l1,h2,l2,h3,l3;
    split2(v.x,h0,l0); split2(v.y,h1,l1); split2(v.z,h2,l2); split2(v.w,h3,l3);
    ((__nv_bfloat162*)dh)[2*i]   = __nv_bfloat162(h0,h1);
    ((__nv_bfloat162*)dh)[2*i+1] = __nv_bfloat162(h2,h3);
    ((__nv_bfloat162*)dl)[2*i]   = __nv_bfloat162(l0,l1);
    ((__nv_bfloat162*)dl)[2*i+1] = __nv_bfloat162(l2,l3);
}

// ===================== mma.sync split-bf16 GEMM (fused passes) ==============
// C = A@W via D[m,n] = sum_k A[m,k]*Bs[n,k], Bs = W^T [N,K].
// Per K-chunk all 4 tiles (Ah,Al,Bh,Bl) are staged once; the three products
// Ah*Bh + Ah*Bl + Al*Bh accumulate into the same fp32 registers.
struct TJob {
    const __nv_bfloat16 *Ah, *Al;   // [M,K]
    const __nv_bfloat16 *Bh, *Bl;   // [N,K]
    const float* bias;              // len N, nullable
    float* C;                       // [M,N]
    __nv_bfloat16 *Ch, *Cl;         // optional split copy of C
};

// tile: BM=128, BN=128, Kc=32. 8 warps, each 64x32. padded rows of 40 bf16.
#define LDP       40
#define TILE_B    (128 * LDP * 2)        // 10240 bytes per operand tile
#define STAGE_B   (4 * TILE_B)           // Ah, Al, Bh, Bl
#define SMEM_DYN  (2 * STAGE_B)          // double buffer = 81920 bytes

__global__ __launch_bounds__(256, 2)
void tc_gemm(TJob j0, TJob j1, TJob j2, int K, int N) {
    extern __shared__ __align__(16) char smem[];
    const TJob& jb = (blockIdx.z == 0) ? j0 : (blockIdx.z == 1) ? j1 : j2;
    const uint32_t sb = smem_u32(smem);
    const int tid = threadIdx.x;
    const int lane = tid & 31, warp = tid >> 5;
    const int wm = warp & 1, wn = warp >> 1;           // warp tile: 64x32
    const int bm = blockIdx.y * 128, bn = blockIdx.x * 128;
    const int kch = K / 32;

    auto issue = [&](int c) {
        const int k0 = c * 32;
        const uint32_t st = sb + (c & 1) * STAGE_B;
#pragma unroll
        for (int i = 0; i < 8; i++) {
            const int tile = i >> 1;
            const int w = (i & 1) ? (tid + 256) & 511 : tid;
            const int row = w >> 2, c16 = w & 3;
            const __nv_bfloat16* src = (tile == 0) ? jb.Ah : (tile == 1) ? jb.Al
                                     : (tile == 2) ? jb.Bh : jb.Bl;
            const int roff = (tile < 2) ? bm : bn;
            cp_async16(st + tile * TILE_B + (row * LDP + c16 * 8) * 2,
                       src + (size_t)(roff + row) * K + k0 + c16 * 8);
        }
    };

    float acc[4][4][4];
#pragma unroll
    for (int i = 0; i < 4; i++)
#pragma unroll
        for (int j = 0; j < 4; j++)
#pragma unroll
            for (int q = 0; q < 4; q++) acc[i][j][q] = 0.f;

    // A x4 addressing (per mt): lanes 0-15 rows m0-15, lanes 16-31 k+8
    const int arow = lane & 15, acsel = (lane >> 4) * 8;
    // B x4 addressing (per nt-PAIR): lanes 0-7 rows n0-7 k+0, 8-15 rows n0-7 k+8,
    //                                16-23 rows n8-15 k+0, 24-31 rows n8-15 k+8
    const int brow4 = lane & 7;
    const int bksel = ((lane >> 3) & 1) * 8;
    const int bnsel = ((lane >> 4) & 1) * 8;

    issue(0); CP_COMMIT();

    for (int c = 0; c < kch; c++) {
        if (c + 1 < kch) issue(c + 1);
        CP_COMMIT();
        CP_WAIT1();
        __syncthreads();

        const uint32_t st = sb + (c & 1) * STAGE_B;
        const uint32_t ah = st,              al = st + TILE_B;
        const uint32_t bh = st + 2 * TILE_B, bl = st + 3 * TILE_B;
#pragma unroll
        for (int kt = 0; kt < 2; kt++) {
            uint32_t afh[4][4], bfh[2][4], bfl[2][4];   // bf*[p] = fragments for nt=2p,2p+1
#pragma unroll
            for (int mt = 0; mt < 4; mt++)
                ldsm_x4(afh[mt], ah + ((wm * 64 + mt * 16 + arow) * LDP + kt * 16 + acsel) * 2);
#pragma unroll
            for (int p = 0; p < 2; p++) {
                ldsm_x4(bfh[p], bh + ((wn * 32 + p * 16 + bnsel + brow4) * LDP + kt * 16 + bksel) * 2);
                ldsm_x4(bfl[p], bl + ((wn * 32 + p * 16 + bnsel + brow4) * LDP + kt * 16 + bksel) * 2);
            }
#pragma unroll
            for (int mt = 0; mt < 4; mt++)
#pragma unroll
                for (int nt = 0; nt < 4; nt++) {
                    mma16816(acc[mt][nt], afh[mt], &bfh[nt >> 1][(nt & 1) * 2]);
                    mma16816(acc[mt][nt], afh[mt], &bfl[nt >> 1][(nt & 1) * 2]);
                }
            uint32_t afl[4][4];
#pragma unroll
            for (int mt = 0; mt < 4; mt++)
                ldsm_x4(afl[mt], al + ((wm * 64 + mt * 16 + arow) * LDP + kt * 16 + acsel) * 2);
#pragma unroll
            for (int mt = 0; mt < 4; mt++)
#pragma unroll
                for (int nt = 0; nt < 4; nt++)
                    mma16816(acc[mt][nt], afl[mt], &bfh[nt >> 1][(nt & 1) * 2]);
        }
        __syncthreads();
    }

    const int quad = lane >> 2, pair = lane & 3;
#pragma unroll
    for (int mt = 0; mt < 4; mt++) {
#pragma unroll
        for (int h = 0; h < 2; h++) {
            int row = bm + wm * 64 + mt * 16 + quad + h * 8;
            float* crow = jb.C + (size_t)row * N;
#pragma unroll
            for (int nt = 0; nt < 4; nt++) {
                int col = bn + wn * 32 + nt * 8 + pair * 2;
                float v0 = acc[mt][nt][2 * h]     + (jb.bias ? jb.bias[col]     : 0.f);
                float v1 = acc[mt][nt][2 * h + 1] + (jb.bias ? jb.bias[col + 1] : 0.f);
                *(float2*)(crow + col) = make_float2(v0, v1);
                if (jb.Ch) {
                    __nv_bfloat16 h0, l0, h1, l1;
                    split2(v0, h0, l0); split2(v1, h1, l1);
                    *(__nv_bfloat162*)(jb.Ch + (size_t)row * N + col) = __nv_bfloat162(h0, h1);
                    *(__nv_bfloat162*)(jb.Cl + (size_t)row * N + col) = __nv_bfloat162(l0, l1);
                }
            }
        }
    }
}

// ===================== fused GRU gate update ================================
__device__ __forceinline__ float sigm_(float x) { return 1.f / (1.f + expf(-x)); }

__device__ __forceinline__ void gate4(const float4& xz, const float4& xr, const float4& xh,
                                      const float4& rz, const float4& rr, const float4& rh,
                                      float4& hv) {
    float z, r, hg;
    z = sigm_(xz.x + rz.x); r = sigm_(xr.x + rr.x); hg = tanhf(xh.x + r * rh.x); hv.x = z * hv.x + (1.f - z) * hg;
    z = sigm_(xz.y + rz.y); r = sigm_(xr.y + rr.y); hg = tanhf(xh.y + r * rh.y); hv.y = z * hv.y + (1.f - z) * hg;
    z = sigm_(xz.z + rz.z); r = sigm_(xr.z + rr.z); hg = tanhf(xh.z + r * rh.z); hv.z = z * hv.z + (1.f - z) * hg;
    z = sigm_(xz.w + rz.w); r = sigm_(xr.w + rr.w); hg = tanhf(xh.w + r * rh.w); hv.w = z * hv.w + (1.f - z) * hg;
}
__device__ __forceinline__ void store_split4(const float4& hv, __nv_bfloat16* ph, __nv_bfloat16* pl) {
    __nv_bfloat16 a0,b0,a1,b1,a2,b2,a3,b3;
    split2(hv.x,a0,b0); split2(hv.y,a1,b1); split2(hv.z,a2,b2); split2(hv.w,a3,b3);
    *(__nv_bfloat162*)(ph)     = __nv_bfloat162(a0,a1);
    *(__nv_bfloat162*)(ph + 2) = __nv_bfloat162(a2,a3);
    *(__nv_bfloat162*)(pl)     = __nv_bfloat162(b0,b1);
    *(__nv_bfloat162*)(pl + 2) = __nv_bfloat162(b2,b3);
}

__global__ __launch_bounds__(256)
void gru_step(const float* __restrict__ proj,         // [V,H3] x-gates for layer 1
              const int* __restrict__ tgt,
              int t1,                                  // layer-1 update time (or -1)
              const float* __restrict__ in1, float* __restrict__ h1,
              __nv_bfloat16* __restrict__ h1h, __nv_bfloat16* __restrict__ h1l,
              int t2,                                  // layer-2 update time (or -1)
              const float* __restrict__ xg2, const float* __restrict__ in2,
              float* __restrict__ h2,
              __nv_bfloat16* __restrict__ h2h, __nv_bfloat16* __restrict__ h2l,
              __nv_bfloat16* __restrict__ seqh, __nv_bfloat16* __restrict__ seql) {
    int idx = blockIdx.x * 256 + threadIdx.x;     // B*H/4 threads
    int b = idx >> 7;
    int j = (idx & 127) * 4;
    size_t hidx = (size_t)b * HH + j;

    if (t2 >= 0) {
        float4 hv = *(float4*)(h2 + hidx);
        if (tgt[b * TT + t2] != 0) {
            const float* xg = xg2 + (size_t)b * H3;
            const float* in = in2 + (size_t)b * H3;
            gate4(*(const float4*)(xg + j), *(const float4*)(xg + HH + j), *(const float4*)(xg + 2*HH + j),
                  *(const float4*)(in + j), *(const float4*)(in + HH + j), *(const float4*)(in + 2*HH + j), hv);
            *(float4*)(h2 + hidx) = hv;
            store_split4(hv, h2h + hidx, h2l + hidx);
        }
        size_t so = (size_t)b * (TT * HH) + (size_t)t2 * HH + j;
        store_split4(hv, seqh + so, seql + so);   // output == state, even when masked
    }

    if (t1 >= 0 && t1 < TT) {
        int tok = tgt[b * TT + t1];
        if (tok != 0) {
            float4 hv = *(float4*)(h1 + hidx);
            const float* xg = proj + (size_t)tok * H3;
            const float* in = in1 + (size_t)b * H3;
            gate4(*(const float4*)(xg + j), *(const float4*)(xg + HH + j), *(const float4*)(xg + 2*HH + j),
                  *(const float4*)(in + j), *(const float4*)(in + HH + j), *(const float4*)(in + 2*HH + j), hv);
            *(float4*)(h1 + hidx) = hv;
            store_split4(hv, h1h + hidx, h1l + hidx);
        }
    }
}

// ===================== softmax over V=128 ===================================
__global__ __launch_bounds__(256)
void softmax_kernel(float* __restrict__ out) {
    int row  = blockIdx.x * 8 + (threadIdx.x >> 5);
    int lane = threadIdx.x & 31;
    float* p = out + (size_t)row * VV + lane * 4;
    float4 v = *(float4*)p;
    float m = fmaxf(fmaxf(v.x, v.y), fmaxf(v.z, v.w));
#pragma unroll
    for (int o = 16; o > 0; o >>= 1) m = fmaxf(m, __shfl_xor_sync(0xffffffffu, m, o));
    v.x = expf(v.x - m); v.y = expf(v.y - m); v.z = expf(v.z - m); v.w = expf(v.w - m);
    float s = v.x + v.y + v.z + v.w;
#pragma unroll
    for (int o = 16; o > 0; o >>= 1) s += __shfl_xor_sync(0xffffffffu, s, o);
    float inv = 1.f / s;
    v.x *= inv; v.y *= inv; v.z *= inv; v.w *= inv;
    *(float4*)p = v;
}

// ===================== launch ===============================================
static void* sym(const void* s) { void* p; cudaGetSymbolAddress(&p, s); return p; }

extern "C" void kernel_launch(void* const* d_in, const int* in_sizes, int n_in,
                              void* d_out, int out_size) {
    const int*   tgt = (const int*)  d_in[0];
    const float* enc = (const float*)d_in[1];
    const float* Wi1 = (const float*)d_in[2];
    const float* Wi2 = (const float*)d_in[3];
    const float* emb = (const float*)d_in[4];
    const float* k1  = (const float*)d_in[5];
    const float* rk1 = (const float*)d_in[6];
    const float* b1  = (const float*)d_in[7];
    const float* k2  = (const float*)d_in[8];
    const float* rk2 = (const float*)d_in[9];
    const float* b2  = (const float*)d_in[10];
    const float* Wv  = (const float*)d_in[11];
    const float* bv  = (const float*)d_in[12];
    float* out = (float*)d_out;

    float* proj = (float*)sym(g_proj);
    float* h1  = (float*)sym(g_h1);   float* h2  = (float*)sym(g_h2);
    float* in1 = (float*)sym(g_in1);  float* xg2 = (float*)sym(g_xg2);  float* in2 = (float*)sym(g_in2);
    __nv_bfloat16 *h1h=(__nv_bfloat16*)sym(g_h1h), *h1l=(__nv_bfloat16*)sym(g_h1l);
    __nv_bfloat16 *h2h=(__nv_bfloat16*)sym(g_h2h), *h2l=(__nv_bfloat16*)sym(g_h2l);
    __nv_bfloat16 *sqh=(__nv_bfloat16*)sym(g_seqh), *sql=(__nv_bfloat16*)sym(g_seql);
    __nv_bfloat16 *ench=(__nv_bfloat16*)sym(g_ench), *encl=(__nv_bfloat16*)sym(g_encl);
    __nv_bfloat16 *k1h=(__nv_bfloat16*)sym(g_k1h),   *k1l=(__nv_bfloat16*)sym(g_k1l);
    __nv_bfloat16 *rk1h=(__nv_bfloat16*)sym(g_rk1h), *rk1l=(__nv_bfloat16*)sym(g_rk1l);
    __nv_bfloat16 *k2h=(__nv_bfloat16*)sym(g_k2h),   *k2l=(__nv_bfloat16*)sym(g_k2l);
    __nv_bfloat16 *rk2h=(__nv_bfloat16*)sym(g_rk2h), *rk2l=(__nv_bfloat16*)sym(g_rk2l);
    __nv_bfloat16 *wi1h=(__nv_bfloat16*)sym(g_wi1h), *wi1l=(__nv_bfloat16*)sym(g_wi1l);
    __nv_bfloat16 *wi2h=(__nv_bfloat16*)sym(g_wi2h), *wi2l=(__nv_bfloat16*)sym(g_wi2l);
    __nv_bfloat16 *wvh=(__nv_bfloat16*)sym(g_wvh),   *wvl=(__nv_bfloat16*)sym(g_wvl);
    __nv_bfloat16 *embh=(__nv_bfloat16*)sym(g_embh), *embl=(__nv_bfloat16*)sym(g_embl);

    cudaFuncSetAttribute(tc_gemm, cudaFuncAttributeMaxDynamicSharedMemorySize, SMEM_DYN);

    dim3 blk(256);

    // ---- prep ----
    tsplit_kernel<<<dim3(HH/32, ENCC/32),blk>>>(Wi1, wi1h, wi1l, ENCC, HH);
    tsplit_kernel<<<dim3(HH/32, ENCC/32),blk>>>(Wi2, wi2h, wi2l, ENCC, HH);
    split_kernel<<<(BB*ENCC/4 + 255)/256, blk>>>(enc, ench, encl, BB*ENCC/4);
    tsplit_kernel<<<dim3(H3/32, EE/32),  blk>>>(k1,  k1h,  k1l,  EE,   H3);
    split_kernel<<<(VV*EE/4 + 255)/256,   blk>>>(emb, embh, embl, VV*EE/4);

    // h0 init: h1 = enc@Wi1, h2 = enc@Wi2 (with bf16 split outputs)
    {
        TJob a = {ench, encl, wi1h, wi1l, nullptr, h1, h1h, h1l};
        TJob b = {ench, encl, wi2h, wi2l, nullptr, h2, h2h, h2l};
        tc_gemm<<<dim3(HH/128, BB/128, 2), blk, SMEM_DYN>>>(a, b, a, ENCC, HH);
    }

    // remaining prep
    tsplit3_kernel<<<dim3(H3/32, HH/32, 3), blk>>>(rk1, rk1h, rk1l,
                                                   k2,  k2h,  k2l,
                                                   rk2, rk2h, rk2l);
    tsplit_kernel<<<dim3(VV/32, HH/32),  blk>>>(Wv,  wvh,  wvl,  HH,   VV);

    // proj = emb_table @ k1 + b1[0]  (V=128 rows only)
    {
        TJob a = {embh, embl, k1h, k1l, b1, proj, nullptr, nullptr};
        tc_gemm<<<dim3(H3/128, 1, 1), blk, SMEM_DYN>>>(a, a, a, EE, H3);
    }
    // inner1(t=0) = h1 @ rk1 + b1[1]
    {
        TJob a = {h1h, h1l, rk1h, rk1l, b1 + H3, in1, nullptr, nullptr};
        tc_gemm<<<dim3(H3/128, BB/128, 1), blk, SMEM_DYN>>>(a, a, a, HH, H3);
    }
    const int gblocks = BB * HH / 4 / 256;  // 1024
    // layer-1 update for t=0
    gru_step<<<gblocks, blk>>>(proj, tgt, 0, in1, h1, h1h, h1l,
                               -1, nullptr, nullptr, nullptr, nullptr, nullptr,
                               nullptr, nullptr);

    for (int t = 0; t < TT; t++) {
        // fused GEMM: xg2 = h1@k2+b2[0]; in2 = h2@rk2+b2[1]; in1 = h1@rk1+b1[1] (skip at last t)
        {
            TJob a = {h1h, h1l, k2h,  k2l,  b2,      xg2, nullptr, nullptr};
            TJob b = {h2h, h2l, rk2h, rk2l, b2 + H3, in2, nullptr, nullptr};
            TJob c = {h1h, h1l, rk1h, rk1l, b1 + H3, in1, nullptr, nullptr};
            int nz = (t == TT - 1) ? 2 : 3;   // in1 for t=TT is never consumed
            tc_gemm<<<dim3(H3/128, BB/128, nz), blk, SMEM_DYN>>>(a, b, c, HH, H3);
        }
        // fused elementwise: layer-2 update at t (emit seq2[t]) + layer-1 update at t+1
        gru_step<<<gblocks, blk>>>(proj, tgt, t + 1, in1, h1, h1h, h1l,
                                   t, xg2, in2, h2, h2h, h2l, sqh, sql);
    }

    // ---- logits = seq2 @ Wv + bv, then softmax (in d_out) ----
    {
        TJob a = {sqh, sql, wvh, wvl, bv, out, nullptr, nullptr};
        tc_gemm<<<dim3(VV/128, (BB*TT)/128, 1), blk, SMEM_DYN>>>(a, a, a, HH, VV);
    }
    softmax_kernel<<<(BB*TT)/8, blk>>>(out);
}